// round 14
// baseline (speedup 1.0000x reference)
#include <cuda_runtime.h>
#include <math.h>

#define NB 16
#define NS 512
#define NH 16
#define ND 64
#define NHID 1024
#define NROW (NB*NS)        // 8192
#define NBH (NB*NH)         // 256
#define NTOK (NBH*NS*ND)    // 8388608

// ---------------- scratch ----------------
__device__ __align__(16) float g_proj[2][NROW*NHID];
__device__ __align__(16) float g_c[2][NTOK];           // (B,H,S,D)
__device__ __align__(16) float g_q[2][NTOK];
__device__ __align__(16) float g_k[2][NTOK];
__device__ __align__(16) float g_v[2][NTOK];
__device__ __align__(16) float g_o[2][NTOK];

// ---------------- tf32 mma helpers ----------------
__device__ __forceinline__ unsigned cvt_tf32(float x) {
    unsigned u; asm("cvt.rna.tf32.f32 %0, %1;" : "=r"(u) : "f"(x)); return u;
}
__device__ __forceinline__ float tf32f(float x) {
    return __uint_as_float(cvt_tf32(x));
}
__device__ __forceinline__ void mma_tf32(float c[4], const unsigned a[4], unsigned b0, unsigned b1) {
    asm("mma.sync.aligned.m16n8k8.row.col.f32.tf32.tf32.f32 "
        "{%0,%1,%2,%3}, {%4,%5,%6,%7}, {%8,%9}, {%0,%1,%2,%3};"
        : "+f"(c[0]), "+f"(c[1]), "+f"(c[2]), "+f"(c[3])
        : "r"(a[0]), "r"(a[1]), "r"(a[2]), "r"(a[3]), "r"(b0), "r"(b1));
}
// column-pair permutation: within each 8-col group, logical (t, t+4) -> physical (2t, 2t+1)
// for a float4 at logical col cc (cc%4==0): base = (cc&~7)|((cc>>2)&1), elements at base+0,2,4,6
#define PBASE(cc) (((cc) & ~7) | (((cc) >> 2) & 1))

// ============ big projection GEMM (tf32, permuted pair fragments) ============
#define GPA 36     // 36 mod 32 = 4 -> pair loads hit banks 4g+2t : conflict-free
__global__ void gemm_tf32_kernel(const float* __restrict__ A,
                                 const float* __restrict__ W,
                                 const float* __restrict__ bias,
                                 int K, int which) {
    __shared__ __align__(16) float As[128*GPA];
    __shared__ __align__(16) float Ws[128*GPA];
    float* C = g_proj[which];
    int tid = threadIdx.x;
    int wid = tid >> 5, lane = tid & 31;
    int wm = wid >> 1, wn = wid & 1;
    int g = lane >> 2, t = lane & 3;
    int m0 = blockIdx.y * 128, n0 = blockIdx.x * 128;
    int lr = tid >> 3;
    int lc = (tid & 7) * 4;
    int pb = PBASE(lc);
    float acc[2][8][4] = {};
    for (int k0 = 0; k0 < K; k0 += 32) {
        #pragma unroll
        for (int i = 0; i < 4; i++) {
            int r = lr + i*32;
            float4 av = *(const float4*)(A + (size_t)(m0 + r)*K + k0 + lc);
            float4 wv = *(const float4*)(W + (size_t)(n0 + r)*K + k0 + lc);
            float* ad = As + r*GPA + pb;
            float* wd = Ws + r*GPA + pb;
            ad[0]=tf32f(av.x); ad[2]=tf32f(av.y); ad[4]=tf32f(av.z); ad[6]=tf32f(av.w);
            wd[0]=tf32f(wv.x); wd[2]=tf32f(wv.y); wd[4]=tf32f(wv.z); wd[6]=tf32f(wv.w);
        }
        __syncthreads();
        #pragma unroll
        for (int kc = 0; kc < 4; kc++) {
            unsigned a[2][4];
            #pragma unroll
            for (int mf = 0; mf < 2; mf++) {
                const float* ab = As + (wm*32 + mf*16 + g)*GPA + kc*8 + 2*t;
                float2 a01 = *(const float2*)ab;
                float2 a23 = *(const float2*)(ab + 8*GPA);
                a[mf][0] = __float_as_uint(a01.x);
                a[mf][1] = __float_as_uint(a23.x);
                a[mf][2] = __float_as_uint(a01.y);
                a[mf][3] = __float_as_uint(a23.y);
            }
            #pragma unroll
            for (int nf = 0; nf < 8; nf++) {
                float2 bp = *(const float2*)(Ws + (wn*64 + nf*8 + g)*GPA + kc*8 + 2*t);
                unsigned b0 = __float_as_uint(bp.x);
                unsigned b1 = __float_as_uint(bp.y);
                mma_tf32(acc[0][nf], a[0], b0, b1);
                mma_tf32(acc[1][nf], a[1], b0, b1);
            }
        }
        __syncthreads();
    }
    #pragma unroll
    for (int mf = 0; mf < 2; mf++) {
        int r0 = m0 + wm*32 + mf*16 + g;
        #pragma unroll
        for (int nf = 0; nf < 8; nf++) {
            int c = n0 + wn*64 + nf*8 + 2*t;
            float bx = bias[c], by = bias[c+1];
            *(float2*)(C + (size_t)r0*NHID + c) =
                make_float2(acc[mf][nf][0] + bx, acc[mf][nf][1] + by);
            *(float2*)(C + (size_t)(r0+8)*NHID + c) =
                make_float2(acc[mf][nf][2] + bx, acc[mf][nf][3] + by);
        }
    }
}

// ---------------- LN + l2-normalize + D^-0.5 (merged both directions) ----------------
__device__ __forceinline__ float breduce256(float v, float* red) {
    #pragma unroll
    for (int o = 16; o > 0; o >>= 1) v += __shfl_xor_sync(0xffffffffu, v, o);
    int tid = threadIdx.x;
    if ((tid & 31) == 0) red[tid >> 5] = v;
    __syncthreads();
    float t = 0.f;
    #pragma unroll
    for (int i = 0; i < 8; i++) t += red[i];
    __syncthreads();
    return t;
}

__global__ void ln_l2_kernel(const float* __restrict__ g0, const float* __restrict__ b0,
                             const float* __restrict__ g1, const float* __restrict__ b1) {
    __shared__ float red[8];
    int which = blockIdx.y;
    const float* g = which ? g1 : g0;
    const float* b = which ? b1 : b0;
    int row = blockIdx.x;
    int tid = threadIdx.x;
    const float* y = g_proj[which] + (size_t)row * NHID;
    float v[4], sum = 0.f;
    #pragma unroll
    for (int i=0;i<4;i++){ v[i] = y[tid + i*256]; sum += v[i]; }
    sum = breduce256(sum, red);
    float mu = sum * (1.f/NHID);
    float sq = 0.f;
    #pragma unroll
    for (int i=0;i<4;i++){ float d = v[i]-mu; sq += d*d; }
    sq = breduce256(sq, red);
    float rstd = rsqrtf(sq*(1.f/NHID) + 1e-5f);
    float ln[4], s2 = 0.f;
    #pragma unroll
    for (int i=0;i<4;i++){ int n = tid+i*256; ln[i] = (v[i]-mu)*rstd*g[n] + b[n]; s2 += ln[i]*ln[i]; }
    s2 = breduce256(s2, red);
    float scale = 0.125f / fmaxf(sqrtf(s2), 1e-12f);
    int bb = row >> 9, s = row & 511;
    float* outp = g_c[which];
    #pragma unroll
    for (int i=0;i<4;i++){
        int n = tid + i*256;
        int h = n >> 6, d = n & 63;
        outp[(((size_t)(bb*NH + h))*NS + s)*ND + d] = ln[i]*scale;
    }
}

// ============ per-head QKV projection (permuted pair fragments, high-occ) ============
#define QPA 68     // 68 mod 32 = 4 -> conflict-free pair loads
__global__ void __launch_bounds__(256, 4)
qkv_tf32_kernel(const float* __restrict__ w_i2t, const float* __restrict__ b_i2t,
                const float* __restrict__ w_t2i, const float* __restrict__ b_t2i) {
    extern __shared__ __align__(16) float sm[];
    float* Xq  = sm;
    float* Xkv = sm + 64*QPA;
    float* Wsm = sm + 2*64*QPA;
    int which = blockIdx.z;
    const float* in_w = which ? w_t2i : w_i2t;
    const float* in_b = which ? b_t2i : b_i2t;
    int bh = blockIdx.y;
    int h = bh & (NH-1);
    int s0 = blockIdx.x * 64;
    int tid = threadIdx.x;
    int wid = tid >> 5, lane = tid & 31;
    int wm = wid >> 1, wn = wid & 1;
    int g = lane >> 2, t = lane & 3;
    int fr0 = wm*16 + g;
    int lr = tid >> 4;
    int lc = (tid & 15) * 4;
    int pb = PBASE(lc);
    const float* qbase  = g_c[which]   + ((size_t)bh*NS + s0)*ND;
    const float* kvbase = g_c[which^1] + ((size_t)bh*NS + s0)*ND;
    #pragma unroll
    for (int i = 0; i < 4; i++) {
        int r = lr + i*16;
        float4 a  = *(const float4*)(qbase  + r*ND + lc);
        float4 kv = *(const float4*)(kvbase + r*ND + lc);
        float* qd = Xq + r*QPA + pb;
        float* kd = Xkv + r*QPA + pb;
        qd[0]=tf32f(a.x);  qd[2]=tf32f(a.y);  qd[4]=tf32f(a.z);  qd[6]=tf32f(a.w);
        kd[0]=tf32f(kv.x); kd[2]=tf32f(kv.y); kd[4]=tf32f(kv.z); kd[6]=tf32f(kv.w);
    }
    for (int p = 0; p < 3; p++) {
        __syncthreads();
        const float* wsrc = in_w + ((size_t)h*192 + p*64)*64;
        #pragma unroll
        for (int i = 0; i < 4; i++) {
            int r = lr + i*16;
            float4 w = *(const float4*)(wsrc + r*64 + lc);
            float* wd = Wsm + r*QPA + pb;
            wd[0]=tf32f(w.x); wd[2]=tf32f(w.y); wd[4]=tf32f(w.z); wd[6]=tf32f(w.w);
        }
        __syncthreads();
        const float* Xs = (p == 0) ? Xq : Xkv;
        float acc[4][4] = {};
        #pragma unroll
        for (int kc = 0; kc < 8; kc++) {
            const float* ab = Xs + fr0*QPA + kc*8 + 2*t;
            float2 a01 = *(const float2*)ab;
            float2 a23 = *(const float2*)(ab + 8*QPA);
            unsigned a[4];
            a[0] = __float_as_uint(a01.x);
            a[1] = __float_as_uint(a23.x);
            a[2] = __float_as_uint(a01.y);
            a[3] = __float_as_uint(a23.y);
            #pragma unroll
            for (int nt = 0; nt < 4; nt++) {
                float2 bp = *(const float2*)(Wsm + (wn*32 + nt*8 + g)*QPA + kc*8 + 2*t);
                mma_tf32(acc[nt], a, __float_as_uint(bp.x), __float_as_uint(bp.y));
            }
        }
        float* dst = (p==0) ? g_q[which] : (p==1) ? g_k[which] : g_v[which];
        float qscale = (p==0) ? 0.125f : 1.f;
        const float* bsrc = in_b + h*192 + p*64;
        #pragma unroll
        for (int nt = 0; nt < 4; nt++) {
            int c = wn*32 + nt*8 + 2*t;
            float bx = bsrc[c], by = bsrc[c+1];
            float* o0 = dst + ((size_t)bh*NS + s0 + fr0)*ND + c;
            float* o1 = dst + ((size_t)bh*NS + s0 + fr0 + 8)*ND + c;
            *(float2*)o0 = make_float2((acc[nt][0]+bx)*qscale, (acc[nt][1]+by)*qscale);
            *(float2*)o1 = make_float2((acc[nt][2]+bx)*qscale, (acc[nt][3]+by)*qscale);
        }
    }
}

// ============ flash attention: permuted-pair K (QK^T), proven R12 P@V path ============
#define KPAD 68   // 68 mod 32 = 4 -> pair loads conflict-free
#define VPAD 72   // 72 mod 32 = 8 -> scalar V loads (8t+g) conflict-free
__global__ void __launch_bounds__(256, 2) attn_kernel() {
    __shared__ __align__(16) float ks[64*KPAD];
    __shared__ __align__(16) float vs[64*VPAD];
    int which = blockIdx.z;
    const float* Q = g_q[which];
    const float* K = g_k[which];
    const float* V = g_v[which];
    float* O = g_o[which];
    int bh = blockIdx.y;
    int q0 = blockIdx.x * 128;
    int tid = threadIdx.x, wid = tid >> 5, lane = tid & 31;
    int g = lane >> 2, t = lane & 3;

    // ---- stage Q (128 x 64, tf32, permuted cols) into ks/vs scratch ----
    {
        int r = tid >> 1;
        int c0 = (tid & 1) * 32;
        const float* src = Q + ((size_t)bh*NS + q0 + r)*ND + c0;
        float* dst = (r < 64) ? (ks + r*KPAD) : (vs + (r-64)*VPAD);
        #pragma unroll
        for (int i = 0; i < 8; i++) {
            float4 v4 = *(const float4*)(src + i*4);
            int b = PBASE(c0 + i*4);
            dst[b+0]=tf32f(v4.x); dst[b+2]=tf32f(v4.y);
            dst[b+4]=tf32f(v4.z); dst[b+6]=tf32f(v4.w);
        }
    }
    __syncthreads();
    unsigned qf[8][4];
    {
        int rq = wid*16 + g;
        const float* base = (rq < 64) ? (ks + rq*KPAD) : (vs + (rq-64)*VPAD);
        int stride = (rq < 64) ? KPAD : VPAD;
        #pragma unroll
        for (int kc = 0; kc < 8; kc++) {
            float2 p0 = *(const float2*)(base + kc*8 + 2*t);
            float2 p1 = *(const float2*)(base + 8*stride + kc*8 + 2*t);
            qf[kc][0] = __float_as_uint(p0.x);
            qf[kc][1] = __float_as_uint(p1.x);
            qf[kc][2] = __float_as_uint(p0.y);
            qf[kc][3] = __float_as_uint(p1.y);
        }
    }
    __syncthreads();

    float of[8][4] = {};
    float m0 = -1e30f, m1 = -1e30f, l0 = 0.f, l1 = 0.f;

    for (int j0 = 0; j0 < NS; j0 += 64) {
        // ---- stage K (permuted cols) and V (plain row-major) ----
        {
            int r = tid >> 2, c0 = (tid & 3) * 16;
            const float* ksrc = K + ((size_t)bh*NS + j0 + r)*ND + c0;
            const float* vsrc = V + ((size_t)bh*NS + j0 + r)*ND + c0;
            float* kd = ks + r*KPAD;
            float* vd = vs + r*VPAD;
            #pragma unroll
            for (int i = 0; i < 4; i++) {
                float4 kv = *(const float4*)(ksrc + i*4);
                float4 vv = *(const float4*)(vsrc + i*4);
                int b = PBASE(c0 + i*4);
                kd[b+0]=tf32f(kv.x); kd[b+2]=tf32f(kv.y);
                kd[b+4]=tf32f(kv.z); kd[b+6]=tf32f(kv.w);
                vd[c0+i*4+0]=tf32f(vv.x); vd[c0+i*4+1]=tf32f(vv.y);
                vd[c0+i*4+2]=tf32f(vv.z); vd[c0+i*4+3]=tf32f(vv.w);
            }
        }
        __syncthreads();

        // ---- S = Q @ K^T (pair-loaded B fragments) ----
        float s[8][4] = {};
        #pragma unroll
        for (int nt = 0; nt < 8; nt++) {
            const float* bb = ks + (nt*8 + g)*KPAD;
            #pragma unroll
            for (int kc = 0; kc < 8; kc++) {
                float2 bp = *(const float2*)(bb + kc*8 + 2*t);
                mma_tf32(s[nt], qf[kc], __float_as_uint(bp.x), __float_as_uint(bp.y));
            }
        }

        // ---- register online softmax ----
        float mx0 = -1e30f, mx1 = -1e30f;
        #pragma unroll
        for (int nt = 0; nt < 8; nt++) {
            mx0 = fmaxf(mx0, fmaxf(s[nt][0], s[nt][1]));
            mx1 = fmaxf(mx1, fmaxf(s[nt][2], s[nt][3]));
        }
        mx0 = fmaxf(mx0, __shfl_xor_sync(0xffffffffu, mx0, 1));
        mx0 = fmaxf(mx0, __shfl_xor_sync(0xffffffffu, mx0, 2));
        mx1 = fmaxf(mx1, __shfl_xor_sync(0xffffffffu, mx1, 1));
        mx1 = fmaxf(mx1, __shfl_xor_sync(0xffffffffu, mx1, 2));
        float mn0 = fmaxf(m0, mx0), mn1 = fmaxf(m1, mx1);
        float f0 = __expf(m0 - mn0), f1 = __expf(m1 - mn1);
        float sum0 = 0.f, sum1 = 0.f;
        #pragma unroll
        for (int nt = 0; nt < 8; nt++) {
            float e0 = __expf(s[nt][0] - mn0);
            float e1 = __expf(s[nt][1] - mn0);
            float e2 = __expf(s[nt][2] - mn1);
            float e3 = __expf(s[nt][3] - mn1);
            sum0 += e0 + e1; sum1 += e2 + e3;
            s[nt][0] = tf32f(e0); s[nt][1] = tf32f(e1);
            s[nt][2] = tf32f(e2); s[nt][3] = tf32f(e3);
        }
        sum0 += __shfl_xor_sync(0xffffffffu, sum0, 1);
        sum0 += __shfl_xor_sync(0xffffffffu, sum0, 2);
        sum1 += __shfl_xor_sync(0xffffffffu, sum1, 1);
        sum1 += __shfl_xor_sync(0xffffffffu, sum1, 2);
        l0 = l0*f0 + sum0; l1 = l1*f1 + sum1;
        m0 = mn0; m1 = mn1;
        #pragma unroll
        for (int nt = 0; nt < 8; nt++) {
            of[nt][0] *= f0; of[nt][1] *= f0;
            of[nt][2] *= f1; of[nt][3] *= f1;
        }

        // ---- O += P @ V (R12-proven: shuffles + scalar conflict-free V loads) ----
        int src0 = (lane & ~3) | (t >> 1);
        int src1 = src0 + 2;
        bool odd = (t & 1);
        #pragma unroll
        for (int kc = 0; kc < 8; kc++) {
            float v00 = __shfl_sync(0xffffffffu, s[kc][0], src0);
            float v01 = __shfl_sync(0xffffffffu, s[kc][1], src0);
            float v10 = __shfl_sync(0xffffffffu, s[kc][2], src0);
            float v11 = __shfl_sync(0xffffffffu, s[kc][3], src0);
            float w00 = __shfl_sync(0xffffffffu, s[kc][0], src1);
            float w01 = __shfl_sync(0xffffffffu, s[kc][1], src1);
            float w10 = __shfl_sync(0xffffffffu, s[kc][2], src1);
            float w11 = __shfl_sync(0xffffffffu, s[kc][3], src1);
            unsigned a[4];
            a[0] = __float_as_uint(odd ? v01 : v00);
            a[1] = __float_as_uint(odd ? v11 : v10);
            a[2] = __float_as_uint(odd ? w01 : w00);
            a[3] = __float_as_uint(odd ? w11 : w10);
            const float* vb0 = vs + (kc*8 + t)*VPAD + g;
            const float* vb1 = vs + (kc*8 + t + 4)*VPAD + g;
            #pragma unroll
            for (int nt = 0; nt < 8; nt++) {
                unsigned b0 = __float_as_uint(vb0[nt*8]);
                unsigned b1 = __float_as_uint(vb1[nt*8]);
                mma_tf32(of[nt], a, b0, b1);
            }
        }
        __syncthreads();
    }

    // ---- epilogue ----
    float il0 = 1.f / l0, il1 = 1.f / l1;
    int r0 = wid*16 + g;
    #pragma unroll
    for (int nt = 0; nt < 8; nt++) {
        int c = nt*8 + 2*t;
        float* o0 = O + ((size_t)bh*NS + q0 + r0)*ND + c;
        float* o1 = o0 + 8*ND;
        *(float2*)o0 = make_float2(of[nt][0]*il0, of[nt][1]*il0);
        *(float2*)o1 = make_float2(of[nt][2]*il1, of[nt][3]*il1);
    }
}

// ============ fused out-projection (both dirs) + residual + final LN ============
#define CSTR 132
__global__ void outproj_ln_kernel(const float* __restrict__ w0, const float* __restrict__ bw0,
                                  const float* __restrict__ w1, const float* __restrict__ bw1,
                                  const float* __restrict__ hg, const float* __restrict__ hb,
                                  float* __restrict__ out) {
    extern __shared__ __align__(16) float sm[];
    float* Xs0 = sm;
    float* Ws0 = sm + 64*QPA;
    float* Xs1 = sm + 2*64*QPA;
    float* Ws1 = sm + 3*64*QPA;
    float* comb = sm;                // reused after compute: 64 x CSTR (8448 <= 2*64*68=8704)
    int bh = blockIdx.y, h = bh & (NH-1), s0 = blockIdx.x*64;
    int tid = threadIdx.x;
    int wid = tid >> 5, lane = tid & 31;
    int wm = wid >> 1, wn = wid & 1;
    int g = lane >> 2, t = lane & 3;
    int fr0 = wm*16 + g;
    int lr = tid >> 4, lc = (tid & 15) * 4;
    int pb = PBASE(lc);
    const float* x0 = g_o[0] + ((size_t)bh*NS + s0)*ND;
    const float* x1 = g_o[1] + ((size_t)bh*NS + s0)*ND;
    const float* ws0 = w0 + (size_t)h*64*64;
    const float* ws1 = w1 + (size_t)h*64*64;
    #pragma unroll
    for (int i = 0; i < 4; i++) {
        int r = lr + i*16;
        float4 a0 = *(const float4*)(x0  + r*ND + lc);
        float4 a1 = *(const float4*)(x1  + r*ND + lc);
        float4 v0 = *(const float4*)(ws0 + r*64 + lc);
        float4 v1 = *(const float4*)(ws1 + r*64 + lc);
        float* d;
        d = Xs0 + r*QPA + pb; d[0]=tf32f(a0.x); d[2]=tf32f(a0.y); d[4]=tf32f(a0.z); d[6]=tf32f(a0.w);
        d = Ws0 + r*QPA + pb; d[0]=tf32f(v0.x); d[2]=tf32f(v0.y); d[4]=tf32f(v0.z); d[6]=tf32f(v0.w);
        d = Xs1 + r*QPA + pb; d[0]=tf32f(a1.x); d[2]=tf32f(a1.y); d[4]=tf32f(a1.z); d[6]=tf32f(a1.w);
        d = Ws1 + r*QPA + pb; d[0]=tf32f(v1.x); d[2]=tf32f(v1.y); d[4]=tf32f(v1.z); d[6]=tf32f(v1.w);
    }
    __syncthreads();
    float acc0[4][4] = {}, acc1[4][4] = {};
    #pragma unroll
    for (int kc = 0; kc < 8; kc++) {
        const float* ab0 = Xs0 + fr0*QPA + kc*8 + 2*t;
        const float* ab1 = Xs1 + fr0*QPA + kc*8 + 2*t;
        float2 p00 = *(const float2*)ab0;
        float2 p01 = *(const float2*)(ab0 + 8*QPA);
        float2 p10 = *(const float2*)ab1;
        float2 p11 = *(const float2*)(ab1 + 8*QPA);
        unsigned a0[4], a1[4];
        a0[0]=__float_as_uint(p00.x); a0[1]=__float_as_uint(p01.x);
        a0[2]=__float_as_uint(p00.y); a0[3]=__float_as_uint(p01.y);
        a1[0]=__float_as_uint(p10.x); a1[1]=__float_as_uint(p11.x);
        a1[2]=__float_as_uint(p10.y); a1[3]=__float_as_uint(p11.y);
        #pragma unroll
        for (int nt = 0; nt < 4; nt++) {
            float2 b0 = *(const float2*)(Ws0 + (wn*32 + nt*8 + g)*QPA + kc*8 + 2*t);
            float2 b1 = *(const float2*)(Ws1 + (wn*32 + nt*8 + g)*QPA + kc*8 + 2*t);
            mma_tf32(acc0[nt], a0, __float_as_uint(b0.x), __float_as_uint(b0.y));
            mma_tf32(acc1[nt], a1, __float_as_uint(b1.x), __float_as_uint(b1.y));
        }
    }
    __syncthreads();   // all smem reads done; comb overlays Xs0/Ws0
    const float* r0p = g_c[0] + ((size_t)bh*NS + s0)*ND;
    const float* r1p = g_c[1] + ((size_t)bh*NS + s0)*ND;
    #pragma unroll
    for (int nt = 0; nt < 4; nt++) {
        int c = wn*32 + nt*8 + 2*t;
        float b0x = bw0[h*64+c], b0y = bw0[h*64+c+1];
        float b1x = bw1[h*64+c], b1y = bw1[h*64+c+1];
        int ra = fr0, rb = fr0 + 8;
        float2 ra0 = *(const float2*)(r0p + ra*ND + c);
        float2 rb0 = *(const float2*)(r0p + rb*ND + c);
        float2 ra1 = *(const float2*)(r1p + ra*ND + c);
        float2 rb1 = *(const float2*)(r1p + rb*ND + c);
        *(float2*)(comb + ra*CSTR + c)      = make_float2(acc0[nt][0]+b0x+ra0.x, acc0[nt][1]+b0y+ra0.y);
        *(float2*)(comb + rb*CSTR + c)      = make_float2(acc0[nt][2]+b0x+rb0.x, acc0[nt][3]+b0y+rb0.y);
        *(float2*)(comb + ra*CSTR + 64 + c) = make_float2(acc1[nt][0]+b1x+ra1.x, acc1[nt][1]+b1y+ra1.y);
        *(float2*)(comb + rb*CSTR + 64 + c) = make_float2(acc1[nt][2]+b1x+rb1.x, acc1[nt][3]+b1y+rb1.y);
    }
    __syncthreads();
    // LayerNorm over 128: 4 threads per row
    {
        int r = tid >> 2, q = tid & 3;
        const float* prow = comb + r*CSTR + q*32;
        float v[32];
        float sum = 0.f;
        #pragma unroll
        for (int i = 0; i < 8; i++) {
            float4 v4 = *(const float4*)(prow + i*4);
            v[i*4+0]=v4.x; v[i*4+1]=v4.y; v[i*4+2]=v4.z; v[i*4+3]=v4.w;
            sum += v4.x + v4.y + v4.z + v4.w;
        }
        sum += __shfl_xor_sync(0xffffffffu, sum, 1);
        sum += __shfl_xor_sync(0xffffffffu, sum, 2);
        float mu = sum * (1.f/128.f);
        float sq = 0.f;
        #pragma unroll
        for (int i = 0; i < 32; i++) { float d = v[i]-mu; sq += d*d; }
        sq += __shfl_xor_sync(0xffffffffu, sq, 1);
        sq += __shfl_xor_sync(0xffffffffu, sq, 2);
        float rstd = rsqrtf(sq*(1.f/128.f) + 1e-5f);
        float* orow = out + ((size_t)bh*NS + s0 + r)*128 + q*32;
        const float* gg = hg + h*128 + q*32;
        const float* bb = hb + h*128 + q*32;
        #pragma unroll
        for (int i = 0; i < 8; i++) {
            float4 g4 = *(const float4*)(gg + i*4);
            float4 b4 = *(const float4*)(bb + i*4);
            float4 o4;
            o4.x = (v[i*4+0]-mu)*rstd*g4.x + b4.x;
            o4.y = (v[i*4+1]-mu)*rstd*g4.y + b4.y;
            o4.z = (v[i*4+2]-mu)*rstd*g4.z + b4.z;
            o4.w = (v[i*4+3]-mu)*rstd*g4.w + b4.w;
            *(float4*)(orow + i*4) = o4;
        }
    }
}

// ---------------- launch ----------------
extern "C" void kernel_launch(void* const* d_in, const int* in_sizes, int n_in,
                              void* d_out, int out_size) {
    const float* image     = (const float*)d_in[0];
    const float* text      = (const float*)d_in[1];
    const float* img_w     = (const float*)d_in[2];
    const float* img_b     = (const float*)d_in[3];
    const float* img_g     = (const float*)d_in[4];
    const float* img_lb    = (const float*)d_in[5];
    const float* txt_w     = (const float*)d_in[6];
    const float* txt_b     = (const float*)d_in[7];
    const float* txt_g     = (const float*)d_in[8];
    const float* txt_lb    = (const float*)d_in[9];
    const float* i2t_in_w  = (const float*)d_in[10];
    const float* i2t_in_b  = (const float*)d_in[11];
    const float* i2t_out_w = (const float*)d_in[12];
    const float* i2t_out_b = (const float*)d_in[13];
    const float* t2i_in_w  = (const float*)d_in[14];
    const float* t2i_in_b  = (const float*)d_in[15];
    const float* t2i_out_w = (const float*)d_in[16];
    const float* t2i_out_b = (const float*)d_in[17];
    const float* hn_g      = (const float*)d_in[18];
    const float* hn_b      = (const float*)d_in[19];
    float* out = (float*)d_out;

    const int QKV_SMEM = 3*64*QPA*4;   // 52224 B
    const int OPL_SMEM = 4*64*QPA*4;   // 69632 B
    static int attrs_set = 0;
    if (!attrs_set) {
        cudaFuncSetAttribute(qkv_tf32_kernel, cudaFuncAttributeMaxDynamicSharedMemorySize, QKV_SMEM);
        cudaFuncSetAttribute(outproj_ln_kernel, cudaFuncAttributeMaxDynamicSharedMemorySize, OPL_SMEM);
        attrs_set = 1;
    }

    dim3 thr(256);
    gemm_tf32_kernel<<<dim3(8,64), thr>>>(image, img_w, img_b, 768, 0);
    gemm_tf32_kernel<<<dim3(8,64), thr>>>(text,  txt_w, txt_b, 512, 1);
    ln_l2_kernel<<<dim3(8192,2), thr>>>(img_g, img_lb, txt_g, txt_lb);
    qkv_tf32_kernel<<<dim3(8,256,2), thr, QKV_SMEM>>>(i2t_in_w, i2t_in_b, t2i_in_w, t2i_in_b);
    attn_kernel<<<dim3(4,256,2), thr>>>();
    outproj_ln_kernel<<<dim3(8,256), thr, OPL_SMEM>>>(i2t_out_w, i2t_out_b, t2i_out_w, t2i_out_b,
                                                      hn_g, hn_b, out);
}

// round 15
// speedup vs baseline: 1.0395x; 1.0395x over previous
#include <cuda_runtime.h>
#include <math.h>

#define NB 16
#define NS 512
#define NH 16
#define ND 64
#define NHID 1024
#define NROW (NB*NS)        // 8192
#define NBH (NB*NH)         // 256
#define NTOK (NBH*NS*ND)    // 8388608

// ---------------- scratch ----------------
__device__ __align__(16) float g_proj[2][NROW*NHID];
__device__ __align__(16) float g_c[2][NTOK];           // (B,H,S,D)
__device__ __align__(16) float g_q[2][NTOK];
__device__ __align__(16) float g_k[2][NTOK];
__device__ __align__(16) float g_v[2][NTOK];
__device__ __align__(16) float g_o[2][NTOK];

// ---------------- tf32 mma helpers ----------------
__device__ __forceinline__ unsigned cvt_tf32(float x) {
    unsigned u; asm("cvt.rna.tf32.f32 %0, %1;" : "=r"(u) : "f"(x)); return u;
}
__device__ __forceinline__ float tf32f(float x) {
    return __uint_as_float(cvt_tf32(x));
}
__device__ __forceinline__ void mma_tf32(float c[4], const unsigned a[4], unsigned b0, unsigned b1) {
    asm("mma.sync.aligned.m16n8k8.row.col.f32.tf32.tf32.f32 "
        "{%0,%1,%2,%3}, {%4,%5,%6,%7}, {%8,%9}, {%0,%1,%2,%3};"
        : "+f"(c[0]), "+f"(c[1]), "+f"(c[2]), "+f"(c[3])
        : "r"(a[0]), "r"(a[1]), "r"(a[2]), "r"(a[3]), "r"(b0), "r"(b1));
}
// column-pair permutation: within each 8-col group, logical (t, t+4) -> physical (2t, 2t+1)
#define PBASE(cc) (((cc) & ~7) | (((cc) >> 2) & 1))

// ============ big projection GEMM (tf32, permuted pair fragments) ============
#define GPA 40     // 40 mod 32 = 8 -> half-warp pair loads hit banks 8g+2t : conflict-free
__global__ void gemm_tf32_kernel(const float* __restrict__ A,
                                 const float* __restrict__ W,
                                 const float* __restrict__ bias,
                                 int K, int which) {
    __shared__ __align__(16) float As[128*GPA];
    __shared__ __align__(16) float Ws[128*GPA];
    float* C = g_proj[which];
    int tid = threadIdx.x;
    int wid = tid >> 5, lane = tid & 31;
    int wm = wid >> 1, wn = wid & 1;
    int g = lane >> 2, t = lane & 3;
    int m0 = blockIdx.y * 128, n0 = blockIdx.x * 128;
    int lr = tid >> 3;
    int lc = (tid & 7) * 4;
    int pb = PBASE(lc);
    float acc[2][8][4] = {};
    for (int k0 = 0; k0 < K; k0 += 32) {
        #pragma unroll
        for (int i = 0; i < 4; i++) {
            int r = lr + i*32;
            float4 av = *(const float4*)(A + (size_t)(m0 + r)*K + k0 + lc);
            float4 wv = *(const float4*)(W + (size_t)(n0 + r)*K + k0 + lc);
            float* ad = As + r*GPA + pb;
            float* wd = Ws + r*GPA + pb;
            ad[0]=tf32f(av.x); ad[2]=tf32f(av.y); ad[4]=tf32f(av.z); ad[6]=tf32f(av.w);
            wd[0]=tf32f(wv.x); wd[2]=tf32f(wv.y); wd[4]=tf32f(wv.z); wd[6]=tf32f(wv.w);
        }
        __syncthreads();
        #pragma unroll
        for (int kc = 0; kc < 4; kc++) {
            unsigned a[2][4];
            #pragma unroll
            for (int mf = 0; mf < 2; mf++) {
                const float* ab = As + (wm*32 + mf*16 + g)*GPA + kc*8 + 2*t;
                float2 a01 = *(const float2*)ab;
                float2 a23 = *(const float2*)(ab + 8*GPA);
                a[mf][0] = __float_as_uint(a01.x);
                a[mf][1] = __float_as_uint(a23.x);
                a[mf][2] = __float_as_uint(a01.y);
                a[mf][3] = __float_as_uint(a23.y);
            }
            #pragma unroll
            for (int nf = 0; nf < 8; nf++) {
                float2 bp = *(const float2*)(Ws + (wn*64 + nf*8 + g)*GPA + kc*8 + 2*t);
                unsigned b0 = __float_as_uint(bp.x);
                unsigned b1 = __float_as_uint(bp.y);
                mma_tf32(acc[0][nf], a[0], b0, b1);
                mma_tf32(acc[1][nf], a[1], b0, b1);
            }
        }
        __syncthreads();
    }
    #pragma unroll
    for (int mf = 0; mf < 2; mf++) {
        int r0 = m0 + wm*32 + mf*16 + g;
        #pragma unroll
        for (int nf = 0; nf < 8; nf++) {
            int c = n0 + wn*64 + nf*8 + 2*t;
            float bx = bias[c], by = bias[c+1];
            *(float2*)(C + (size_t)r0*NHID + c) =
                make_float2(acc[mf][nf][0] + bx, acc[mf][nf][1] + by);
            *(float2*)(C + (size_t)(r0+8)*NHID + c) =
                make_float2(acc[mf][nf][2] + bx, acc[mf][nf][3] + by);
        }
    }
}

// ---------------- LN + l2-normalize + D^-0.5 (merged both directions) ----------------
__device__ __forceinline__ float breduce256(float v, float* red) {
    #pragma unroll
    for (int o = 16; o > 0; o >>= 1) v += __shfl_xor_sync(0xffffffffu, v, o);
    int tid = threadIdx.x;
    if ((tid & 31) == 0) red[tid >> 5] = v;
    __syncthreads();
    float t = 0.f;
    #pragma unroll
    for (int i = 0; i < 8; i++) t += red[i];
    __syncthreads();
    return t;
}

__global__ void ln_l2_kernel(const float* __restrict__ g0, const float* __restrict__ b0,
                             const float* __restrict__ g1, const float* __restrict__ b1) {
    __shared__ float red[8];
    int which = blockIdx.y;
    const float* g = which ? g1 : g0;
    const float* b = which ? b1 : b0;
    int row = blockIdx.x;
    int tid = threadIdx.x;
    const float* y = g_proj[which] + (size_t)row * NHID;
    float v[4], sum = 0.f;
    #pragma unroll
    for (int i=0;i<4;i++){ v[i] = y[tid + i*256]; sum += v[i]; }
    sum = breduce256(sum, red);
    float mu = sum * (1.f/NHID);
    float sq = 0.f;
    #pragma unroll
    for (int i=0;i<4;i++){ float d = v[i]-mu; sq += d*d; }
    sq = breduce256(sq, red);
    float rstd = rsqrtf(sq*(1.f/NHID) + 1e-5f);
    float ln[4], s2 = 0.f;
    #pragma unroll
    for (int i=0;i<4;i++){ int n = tid+i*256; ln[i] = (v[i]-mu)*rstd*g[n] + b[n]; s2 += ln[i]*ln[i]; }
    s2 = breduce256(s2, red);
    float scale = 0.125f / fmaxf(sqrtf(s2), 1e-12f);
    int bb = row >> 9, s = row & 511;
    float* outp = g_c[which];
    #pragma unroll
    for (int i=0;i<4;i++){
        int n = tid + i*256;
        int h = n >> 6, d = n & 63;
        outp[(((size_t)(bb*NH + h))*NS + s)*ND + d] = ln[i]*scale;
    }
}

// ============ per-head QKV projection (permuted pair fragments, high-occ) ============
#define QPA 72     // 72 mod 32 = 8 -> conflict-free pair loads
__global__ void __launch_bounds__(256, 4)
qkv_tf32_kernel(const float* __restrict__ w_i2t, const float* __restrict__ b_i2t,
                const float* __restrict__ w_t2i, const float* __restrict__ b_t2i) {
    extern __shared__ __align__(16) float sm[];
    float* Xq  = sm;
    float* Xkv = sm + 64*QPA;
    float* Wsm = sm + 2*64*QPA;
    int which = blockIdx.z;
    const float* in_w = which ? w_t2i : w_i2t;
    const float* in_b = which ? b_t2i : b_i2t;
    int bh = blockIdx.y;
    int h = bh & (NH-1);
    int s0 = blockIdx.x * 64;
    int tid = threadIdx.x;
    int wid = tid >> 5, lane = tid & 31;
    int wm = wid >> 1, wn = wid & 1;
    int g = lane >> 2, t = lane & 3;
    int fr0 = wm*16 + g;
    int lr = tid >> 4;
    int lc = (tid & 15) * 4;
    int pb = PBASE(lc);
    const float* qbase  = g_c[which]   + ((size_t)bh*NS + s0)*ND;
    const float* kvbase = g_c[which^1] + ((size_t)bh*NS + s0)*ND;
    #pragma unroll
    for (int i = 0; i < 4; i++) {
        int r = lr + i*16;
        float4 a  = *(const float4*)(qbase  + r*ND + lc);
        float4 kv = *(const float4*)(kvbase + r*ND + lc);
        float* qd = Xq + r*QPA + pb;
        float* kd = Xkv + r*QPA + pb;
        qd[0]=tf32f(a.x);  qd[2]=tf32f(a.y);  qd[4]=tf32f(a.z);  qd[6]=tf32f(a.w);
        kd[0]=tf32f(kv.x); kd[2]=tf32f(kv.y); kd[4]=tf32f(kv.z); kd[6]=tf32f(kv.w);
    }
    for (int p = 0; p < 3; p++) {
        __syncthreads();
        const float* wsrc = in_w + ((size_t)h*192 + p*64)*64;
        #pragma unroll
        for (int i = 0; i < 4; i++) {
            int r = lr + i*16;
            float4 w = *(const float4*)(wsrc + r*64 + lc);
            float* wd = Wsm + r*QPA + pb;
            wd[0]=tf32f(w.x); wd[2]=tf32f(w.y); wd[4]=tf32f(w.z); wd[6]=tf32f(w.w);
        }
        __syncthreads();
        const float* Xs = (p == 0) ? Xq : Xkv;
        float acc[4][4] = {};
        #pragma unroll
        for (int kc = 0; kc < 8; kc++) {
            const float* ab = Xs + fr0*QPA + kc*8 + 2*t;
            float2 a01 = *(const float2*)ab;
            float2 a23 = *(const float2*)(ab + 8*QPA);
            unsigned a[4];
            a[0] = __float_as_uint(a01.x);
            a[1] = __float_as_uint(a23.x);
            a[2] = __float_as_uint(a01.y);
            a[3] = __float_as_uint(a23.y);
            #pragma unroll
            for (int nt = 0; nt < 4; nt++) {
                float2 bp = *(const float2*)(Wsm + (wn*32 + nt*8 + g)*QPA + kc*8 + 2*t);
                mma_tf32(acc[nt], a, __float_as_uint(bp.x), __float_as_uint(bp.y));
            }
        }
        float* dst = (p==0) ? g_q[which] : (p==1) ? g_k[which] : g_v[which];
        float qscale = (p==0) ? 0.125f : 1.f;
        const float* bsrc = in_b + h*192 + p*64;
        #pragma unroll
        for (int nt = 0; nt < 4; nt++) {
            int c = wn*32 + nt*8 + 2*t;
            float bx = bsrc[c], by = bsrc[c+1];
            float* o0 = dst + ((size_t)bh*NS + s0 + fr0)*ND + c;
            float* o1 = dst + ((size_t)bh*NS + s0 + fr0 + 8)*ND + c;
            *(float2*)o0 = make_float2((acc[nt][0]+bx)*qscale, (acc[nt][1]+by)*qscale);
            *(float2*)o1 = make_float2((acc[nt][2]+bx)*qscale, (acc[nt][3]+by)*qscale);
        }
    }
}

// ============ flash attention: permuted-pair K (QK^T), proven R12 P@V path ============
#define KPAD 72   // 72 mod 32 = 8 -> pair loads conflict-free
#define VPAD 72   // scalar V loads (8t+g = lane-unique banks) conflict-free
__global__ void __launch_bounds__(256, 2) attn_kernel() {
    __shared__ __align__(16) float ks[64*KPAD];
    __shared__ __align__(16) float vs[64*VPAD];
    int which = blockIdx.z;
    const float* Q = g_q[which];
    const float* K = g_k[which];
    const float* V = g_v[which];
    float* O = g_o[which];
    int bh = blockIdx.y;
    int q0 = blockIdx.x * 128;
    int tid = threadIdx.x, wid = tid >> 5, lane = tid & 31;
    int g = lane >> 2, t = lane & 3;

    // ---- stage Q (128 x 64, tf32, permuted cols) into ks/vs scratch ----
    {
        int r = tid >> 1;
        int c0 = (tid & 1) * 32;
        const float* src = Q + ((size_t)bh*NS + q0 + r)*ND + c0;
        float* dst = (r < 64) ? (ks + r*KPAD) : (vs + (r-64)*VPAD);
        #pragma unroll
        for (int i = 0; i < 8; i++) {
            float4 v4 = *(const float4*)(src + i*4);
            int b = PBASE(c0 + i*4);
            dst[b+0]=tf32f(v4.x); dst[b+2]=tf32f(v4.y);
            dst[b+4]=tf32f(v4.z); dst[b+6]=tf32f(v4.w);
        }
    }
    __syncthreads();
    unsigned qf[8][4];
    {
        int rq = wid*16 + g;
        const float* base = (rq < 64) ? (ks + rq*KPAD) : (vs + (rq-64)*VPAD);
        int stride = (rq < 64) ? KPAD : VPAD;
        #pragma unroll
        for (int kc = 0; kc < 8; kc++) {
            float2 p0 = *(const float2*)(base + kc*8 + 2*t);
            float2 p1 = *(const float2*)(base + 8*stride + kc*8 + 2*t);
            qf[kc][0] = __float_as_uint(p0.x);
            qf[kc][1] = __float_as_uint(p1.x);
            qf[kc][2] = __float_as_uint(p0.y);
            qf[kc][3] = __float_as_uint(p1.y);
        }
    }
    __syncthreads();

    float of[8][4] = {};
    float m0 = -1e30f, m1 = -1e30f, l0 = 0.f, l1 = 0.f;

    for (int j0 = 0; j0 < NS; j0 += 64) {
        // ---- stage K (permuted cols) and V (plain row-major) ----
        {
            int r = tid >> 2, c0 = (tid & 3) * 16;
            const float* ksrc = K + ((size_t)bh*NS + j0 + r)*ND + c0;
            const float* vsrc = V + ((size_t)bh*NS + j0 + r)*ND + c0;
            float* kd = ks + r*KPAD;
            float* vd = vs + r*VPAD;
            #pragma unroll
            for (int i = 0; i < 4; i++) {
                float4 kv = *(const float4*)(ksrc + i*4);
                float4 vv = *(const float4*)(vsrc + i*4);
                int b = PBASE(c0 + i*4);
                kd[b+0]=tf32f(kv.x); kd[b+2]=tf32f(kv.y);
                kd[b+4]=tf32f(kv.z); kd[b+6]=tf32f(kv.w);
                vd[c0+i*4+0]=tf32f(vv.x); vd[c0+i*4+1]=tf32f(vv.y);
                vd[c0+i*4+2]=tf32f(vv.z); vd[c0+i*4+3]=tf32f(vv.w);
            }
        }
        __syncthreads();

        // ---- S = Q @ K^T (pair-loaded B fragments) ----
        float s[8][4] = {};
        #pragma unroll
        for (int nt = 0; nt < 8; nt++) {
            const float* bb = ks + (nt*8 + g)*KPAD;
            #pragma unroll
            for (int kc = 0; kc < 8; kc++) {
                float2 bp = *(const float2*)(bb + kc*8 + 2*t);
                mma_tf32(s[nt], qf[kc], __float_as_uint(bp.x), __float_as_uint(bp.y));
            }
        }

        // ---- register online softmax ----
        float mx0 = -1e30f, mx1 = -1e30f;
        #pragma unroll
        for (int nt = 0; nt < 8; nt++) {
            mx0 = fmaxf(mx0, fmaxf(s[nt][0], s[nt][1]));
            mx1 = fmaxf(mx1, fmaxf(s[nt][2], s[nt][3]));
        }
        mx0 = fmaxf(mx0, __shfl_xor_sync(0xffffffffu, mx0, 1));
        mx0 = fmaxf(mx0, __shfl_xor_sync(0xffffffffu, mx0, 2));
        mx1 = fmaxf(mx1, __shfl_xor_sync(0xffffffffu, mx1, 1));
        mx1 = fmaxf(mx1, __shfl_xor_sync(0xffffffffu, mx1, 2));
        float mn0 = fmaxf(m0, mx0), mn1 = fmaxf(m1, mx1);
        float f0 = __expf(m0 - mn0), f1 = __expf(m1 - mn1);
        float sum0 = 0.f, sum1 = 0.f;
        #pragma unroll
        for (int nt = 0; nt < 8; nt++) {
            float e0 = __expf(s[nt][0] - mn0);
            float e1 = __expf(s[nt][1] - mn0);
            float e2 = __expf(s[nt][2] - mn1);
            float e3 = __expf(s[nt][3] - mn1);
            sum0 += e0 + e1; sum1 += e2 + e3;
            s[nt][0] = tf32f(e0); s[nt][1] = tf32f(e1);
            s[nt][2] = tf32f(e2); s[nt][3] = tf32f(e3);
        }
        sum0 += __shfl_xor_sync(0xffffffffu, sum0, 1);
        sum0 += __shfl_xor_sync(0xffffffffu, sum0, 2);
        sum1 += __shfl_xor_sync(0xffffffffu, sum1, 1);
        sum1 += __shfl_xor_sync(0xffffffffu, sum1, 2);
        l0 = l0*f0 + sum0; l1 = l1*f1 + sum1;
        m0 = mn0; m1 = mn1;
        #pragma unroll
        for (int nt = 0; nt < 8; nt++) {
            of[nt][0] *= f0; of[nt][1] *= f0;
            of[nt][2] *= f1; of[nt][3] *= f1;
        }

        // ---- O += P @ V (shuffles + scalar conflict-free V loads) ----
        int src0 = (lane & ~3) | (t >> 1);
        int src1 = src0 + 2;
        bool odd = (t & 1);
        #pragma unroll
        for (int kc = 0; kc < 8; kc++) {
            float v00 = __shfl_sync(0xffffffffu, s[kc][0], src0);
            float v01 = __shfl_sync(0xffffffffu, s[kc][1], src0);
            float v10 = __shfl_sync(0xffffffffu, s[kc][2], src0);
            float v11 = __shfl_sync(0xffffffffu, s[kc][3], src0);
            float w00 = __shfl_sync(0xffffffffu, s[kc][0], src1);
            float w01 = __shfl_sync(0xffffffffu, s[kc][1], src1);
            float w10 = __shfl_sync(0xffffffffu, s[kc][2], src1);
            float w11 = __shfl_sync(0xffffffffu, s[kc][3], src1);
            unsigned a[4];
            a[0] = __float_as_uint(odd ? v01 : v00);
            a[1] = __float_as_uint(odd ? v11 : v10);
            a[2] = __float_as_uint(odd ? w01 : w00);
            a[3] = __float_as_uint(odd ? w11 : w10);
            const float* vb0 = vs + (kc*8 + t)*VPAD + g;
            const float* vb1 = vs + (kc*8 + t + 4)*VPAD + g;
            #pragma unroll
            for (int nt = 0; nt < 8; nt++) {
                unsigned b0 = __float_as_uint(vb0[nt*8]);
                unsigned b1 = __float_as_uint(vb1[nt*8]);
                mma_tf32(of[nt], a, b0, b1);
            }
        }
        __syncthreads();
    }

    // ---- epilogue ----
    float il0 = 1.f / l0, il1 = 1.f / l1;
    int r0 = wid*16 + g;
    #pragma unroll
    for (int nt = 0; nt < 8; nt++) {
        int c = nt*8 + 2*t;
        float* o0 = O + ((size_t)bh*NS + q0 + r0)*ND + c;
        float* o1 = o0 + 8*ND;
        *(float2*)o0 = make_float2(of[nt][0]*il0, of[nt][1]*il0);
        *(float2*)o1 = make_float2(of[nt][2]*il1, of[nt][3]*il1);
    }
}

// ============ fused out-projection (both dirs) + residual + final LN ============
#define CSTR 132
__global__ void outproj_ln_kernel(const float* __restrict__ w0, const float* __restrict__ bw0,
                                  const float* __restrict__ w1, const float* __restrict__ bw1,
                                  const float* __restrict__ hg, const float* __restrict__ hb,
                                  float* __restrict__ out) {
    extern __shared__ __align__(16) float sm[];
    float* Xs0 = sm;
    float* Ws0 = sm + 64*QPA;
    float* Xs1 = sm + 2*64*QPA;
    float* Ws1 = sm + 3*64*QPA;
    float* comb = sm;                // reused after compute: 64 x CSTR (8448 <= 2*64*72=9216)
    int bh = blockIdx.y, h = bh & (NH-1), s0 = blockIdx.x*64;
    int tid = threadIdx.x;
    int wid = tid >> 5, lane = tid & 31;
    int wm = wid >> 1, wn = wid & 1;
    int g = lane >> 2, t = lane & 3;
    int fr0 = wm*16 + g;
    int lr = tid >> 4, lc = (tid & 15) * 4;
    int pb = PBASE(lc);
    const float* x0 = g_o[0] + ((size_t)bh*NS + s0)*ND;
    const float* x1 = g_o[1] + ((size_t)bh*NS + s0)*ND;
    const float* ws0 = w0 + (size_t)h*64*64;
    const float* ws1 = w1 + (size_t)h*64*64;
    #pragma unroll
    for (int i = 0; i < 4; i++) {
        int r = lr + i*16;
        float4 a0 = *(const float4*)(x0  + r*ND + lc);
        float4 a1 = *(const float4*)(x1  + r*ND + lc);
        float4 v0 = *(const float4*)(ws0 + r*64 + lc);
        float4 v1 = *(const float4*)(ws1 + r*64 + lc);
        float* d;
        d = Xs0 + r*QPA + pb; d[0]=tf32f(a0.x); d[2]=tf32f(a0.y); d[4]=tf32f(a0.z); d[6]=tf32f(a0.w);
        d = Ws0 + r*QPA + pb; d[0]=tf32f(v0.x); d[2]=tf32f(v0.y); d[4]=tf32f(v0.z); d[6]=tf32f(v0.w);
        d = Xs1 + r*QPA + pb; d[0]=tf32f(a1.x); d[2]=tf32f(a1.y); d[4]=tf32f(a1.z); d[6]=tf32f(a1.w);
        d = Ws1 + r*QPA + pb; d[0]=tf32f(v1.x); d[2]=tf32f(v1.y); d[4]=tf32f(v1.z); d[6]=tf32f(v1.w);
    }
    __syncthreads();
    float acc0[4][4] = {}, acc1[4][4] = {};
    #pragma unroll
    for (int kc = 0; kc < 8; kc++) {
        const float* ab0 = Xs0 + fr0*QPA + kc*8 + 2*t;
        const float* ab1 = Xs1 + fr0*QPA + kc*8 + 2*t;
        float2 p00 = *(const float2*)ab0;
        float2 p01 = *(const float2*)(ab0 + 8*QPA);
        float2 p10 = *(const float2*)ab1;
        float2 p11 = *(const float2*)(ab1 + 8*QPA);
        unsigned a0[4], a1[4];
        a0[0]=__float_as_uint(p00.x); a0[1]=__float_as_uint(p01.x);
        a0[2]=__float_as_uint(p00.y); a0[3]=__float_as_uint(p01.y);
        a1[0]=__float_as_uint(p10.x); a1[1]=__float_as_uint(p11.x);
        a1[2]=__float_as_uint(p10.y); a1[3]=__float_as_uint(p11.y);
        #pragma unroll
        for (int nt = 0; nt < 4; nt++) {
            float2 b0 = *(const float2*)(Ws0 + (wn*32 + nt*8 + g)*QPA + kc*8 + 2*t);
            float2 b1 = *(const float2*)(Ws1 + (wn*32 + nt*8 + g)*QPA + kc*8 + 2*t);
            mma_tf32(acc0[nt], a0, __float_as_uint(b0.x), __float_as_uint(b0.y));
            mma_tf32(acc1[nt], a1, __float_as_uint(b1.x), __float_as_uint(b1.y));
        }
    }
    __syncthreads();   // all smem reads done; comb overlays Xs0/Ws0
    const float* r0p = g_c[0] + ((size_t)bh*NS + s0)*ND;
    const float* r1p = g_c[1] + ((size_t)bh*NS + s0)*ND;
    #pragma unroll
    for (int nt = 0; nt < 4; nt++) {
        int c = wn*32 + nt*8 + 2*t;
        float b0x = bw0[h*64+c], b0y = bw0[h*64+c+1];
        float b1x = bw1[h*64+c], b1y = bw1[h*64+c+1];
        int ra = fr0, rb = fr0 + 8;
        float2 ra0 = *(const float2*)(r0p + ra*ND + c);
        float2 rb0 = *(const float2*)(r0p + rb*ND + c);
        float2 ra1 = *(const float2*)(r1p + ra*ND + c);
        float2 rb1 = *(const float2*)(r1p + rb*ND + c);
        *(float2*)(comb + ra*CSTR + c)      = make_float2(acc0[nt][0]+b0x+ra0.x, acc0[nt][1]+b0y+ra0.y);
        *(float2*)(comb + rb*CSTR + c)      = make_float2(acc0[nt][2]+b0x+rb0.x, acc0[nt][3]+b0y+rb0.y);
        *(float2*)(comb + ra*CSTR + 64 + c) = make_float2(acc1[nt][0]+b1x+ra1.x, acc1[nt][1]+b1y+ra1.y);
        *(float2*)(comb + rb*CSTR + 64 + c) = make_float2(acc1[nt][2]+b1x+rb1.x, acc1[nt][3]+b1y+rb1.y);
    }
    __syncthreads();
    // LayerNorm over 128: 4 threads per row
    {
        int r = tid >> 2, q = tid & 3;
        const float* prow = comb + r*CSTR + q*32;
        float v[32];
        float sum = 0.f;
        #pragma unroll
        for (int i = 0; i < 8; i++) {
            float4 v4 = *(const float4*)(prow + i*4);
            v[i*4+0]=v4.x; v[i*4+1]=v4.y; v[i*4+2]=v4.z; v[i*4+3]=v4.w;
            sum += v4.x + v4.y + v4.z + v4.w;
        }
        sum += __shfl_xor_sync(0xffffffffu, sum, 1);
        sum += __shfl_xor_sync(0xffffffffu, sum, 2);
        float mu = sum * (1.f/128.f);
        float sq = 0.f;
        #pragma unroll
        for (int i = 0; i < 32; i++) { float d = v[i]-mu; sq += d*d; }
        sq += __shfl_xor_sync(0xffffffffu, sq, 1);
        sq += __shfl_xor_sync(0xffffffffu, sq, 2);
        float rstd = rsqrtf(sq*(1.f/128.f) + 1e-5f);
        float* orow = out + ((size_t)bh*NS + s0 + r)*128 + q*32;
        const float* gg = hg + h*128 + q*32;
        const float* bb = hb + h*128 + q*32;
        #pragma unroll
        for (int i = 0; i < 8; i++) {
            float4 g4 = *(const float4*)(gg + i*4);
            float4 b4 = *(const float4*)(bb + i*4);
            float4 o4;
            o4.x = (v[i*4+0]-mu)*rstd*g4.x + b4.x;
            o4.y = (v[i*4+1]-mu)*rstd*g4.y + b4.y;
            o4.z = (v[i*4+2]-mu)*rstd*g4.z + b4.z;
            o4.w = (v[i*4+3]-mu)*rstd*g4.w + b4.w;
            *(float4*)(orow + i*4) = o4;
        }
    }
}

// ---------------- launch ----------------
extern "C" void kernel_launch(void* const* d_in, const int* in_sizes, int n_in,
                              void* d_out, int out_size) {
    const float* image     = (const float*)d_in[0];
    const float* text      = (const float*)d_in[1];
    const float* img_w     = (const float*)d_in[2];
    const float* img_b     = (const float*)d_in[3];
    const float* img_g     = (const float*)d_in[4];
    const float* img_lb    = (const float*)d_in[5];
    const float* txt_w     = (const float*)d_in[6];
    const float* txt_b     = (const float*)d_in[7];
    const float* txt_g     = (const float*)d_in[8];
    const float* txt_lb    = (const float*)d_in[9];
    const float* i2t_in_w  = (const float*)d_in[10];
    const float* i2t_in_b  = (const float*)d_in[11];
    const float* i2t_out_w = (const float*)d_in[12];
    const float* i2t_out_b = (const float*)d_in[13];
    const float* t2i_in_w  = (const float*)d_in[14];
    const float* t2i_in_b  = (const float*)d_in[15];
    const float* t2i_out_w = (const float*)d_in[16];
    const float* t2i_out_b = (const float*)d_in[17];
    const float* hn_g      = (const float*)d_in[18];
    const float* hn_b      = (const float*)d_in[19];
    float* out = (float*)d_out;

    const int QKV_SMEM = 3*64*QPA*4;   // 55296 B
    const int OPL_SMEM = 4*64*QPA*4;   // 73728 B
    static int attrs_set = 0;
    if (!attrs_set) {
        cudaFuncSetAttribute(qkv_tf32_kernel, cudaFuncAttributeMaxDynamicSharedMemorySize, QKV_SMEM);
        cudaFuncSetAttribute(outproj_ln_kernel, cudaFuncAttributeMaxDynamicSharedMemorySize, OPL_SMEM);
        attrs_set = 1;
    }

    dim3 thr(256);
    gemm_tf32_kernel<<<dim3(8,64), thr>>>(image, img_w, img_b, 768, 0);
    gemm_tf32_kernel<<<dim3(8,64), thr>>>(text,  txt_w, txt_b, 512, 1);
    ln_l2_kernel<<<dim3(8192,2), thr>>>(img_g, img_lb, txt_g, txt_lb);
    qkv_tf32_kernel<<<dim3(8,256,2), thr, QKV_SMEM>>>(i2t_in_w, i2t_in_b, t2i_in_w, t2i_in_b);
    attn_kernel<<<dim3(4,256,2), thr>>>();
    outproj_ln_kernel<<<dim3(8,256), thr, OPL_SMEM>>>(i2t_out_w, i2t_out_b, t2i_out_w, t2i_out_b,
                                                      hn_g, hn_b, out);
}

// round 16
// speedup vs baseline: 1.1932x; 1.1478x over previous
#include <cuda_runtime.h>
#include <math.h>

#define NB 16
#define NS 512
#define NH 16
#define ND 64
#define NHID 1024
#define NROW (NB*NS)        // 8192
#define NBH (NB*NH)         // 256
#define NTOK (NBH*NS*ND)    // 8388608

// ---------------- scratch ----------------
__device__ __align__(16) float g_proj[2][NROW*NHID];
__device__ __align__(16) float g_c[2][NTOK];           // (B,H,S,D)
__device__ __align__(16) float g_q[2][NTOK];
__device__ __align__(16) float g_k[2][NTOK];
__device__ __align__(16) float g_v[2][NTOK];
__device__ __align__(16) float g_o[2][NTOK];

// ---------------- tf32 mma helpers ----------------
__device__ __forceinline__ unsigned cvt_tf32(float x) {
    unsigned u; asm("cvt.rna.tf32.f32 %0, %1;" : "=r"(u) : "f"(x)); return u;
}
__device__ __forceinline__ float tf32f(float x) {
    return __uint_as_float(cvt_tf32(x));
}
__device__ __forceinline__ void mma_tf32(float c[4], const unsigned a[4], unsigned b0, unsigned b1) {
    asm("mma.sync.aligned.m16n8k8.row.col.f32.tf32.tf32.f32 "
        "{%0,%1,%2,%3}, {%4,%5,%6,%7}, {%8,%9}, {%0,%1,%2,%3};"
        : "+f"(c[0]), "+f"(c[1]), "+f"(c[2]), "+f"(c[3])
        : "r"(a[0]), "r"(a[1]), "r"(a[2]), "r"(a[3]), "r"(b0), "r"(b1));
}

// ============ big projection GEMM (tf32 tensor cores) — R12 proven ============
#define GPA 36
__global__ void gemm_tf32_kernel(const float* __restrict__ A,
                                 const float* __restrict__ W,
                                 const float* __restrict__ bias,
                                 int K, int which) {
    __shared__ __align__(16) float As[128*GPA];
    __shared__ __align__(16) float Ws[128*GPA];
    float* C = g_proj[which];
    int tid = threadIdx.x;
    int wid = tid >> 5, lane = tid & 31;
    int wm = wid >> 1, wn = wid & 1;
    int g = lane >> 2, t = lane & 3;
    int m0 = blockIdx.y * 128, n0 = blockIdx.x * 128;
    int lr = tid >> 3;
    int lc = (tid & 7) * 4;
    float acc[2][8][4] = {};
    for (int k0 = 0; k0 < K; k0 += 32) {
        #pragma unroll
        for (int i = 0; i < 4; i++) {
            int r = lr + i*32;
            float4 av = *(const float4*)(A + (size_t)(m0 + r)*K + k0 + lc);
            float4 wv = *(const float4*)(W + (size_t)(n0 + r)*K + k0 + lc);
            float* ad = As + r*GPA + lc;
            float* wd = Ws + r*GPA + lc;
            ad[0]=tf32f(av.x); ad[1]=tf32f(av.y); ad[2]=tf32f(av.z); ad[3]=tf32f(av.w);
            wd[0]=tf32f(wv.x); wd[1]=tf32f(wv.y); wd[2]=tf32f(wv.z); wd[3]=tf32f(wv.w);
        }
        __syncthreads();
        #pragma unroll
        for (int kc = 0; kc < 4; kc++) {
            unsigned a[2][4];
            #pragma unroll
            for (int mf = 0; mf < 2; mf++) {
                const float* ab = As + (wm*32 + mf*16 + g)*GPA + kc*8 + t;
                a[mf][0] = __float_as_uint(ab[0]);
                a[mf][1] = __float_as_uint(ab[8*GPA]);
                a[mf][2] = __float_as_uint(ab[4]);
                a[mf][3] = __float_as_uint(ab[8*GPA+4]);
            }
            #pragma unroll
            for (int nf = 0; nf < 8; nf++) {
                const float* bb = Ws + (wn*64 + nf*8 + g)*GPA + kc*8 + t;
                unsigned b0 = __float_as_uint(bb[0]);
                unsigned b1 = __float_as_uint(bb[4]);
                mma_tf32(acc[0][nf], a[0], b0, b1);
                mma_tf32(acc[1][nf], a[1], b0, b1);
            }
        }
        __syncthreads();
    }
    #pragma unroll
    for (int mf = 0; mf < 2; mf++) {
        int r0 = m0 + wm*32 + mf*16 + g;
        #pragma unroll
        for (int nf = 0; nf < 8; nf++) {
            int c = n0 + wn*64 + nf*8 + 2*t;
            float bx = bias[c], by = bias[c+1];
            *(float2*)(C + (size_t)r0*NHID + c) =
                make_float2(acc[mf][nf][0] + bx, acc[mf][nf][1] + by);
            *(float2*)(C + (size_t)(r0+8)*NHID + c) =
                make_float2(acc[mf][nf][2] + bx, acc[mf][nf][3] + by);
        }
    }
}

// ---------------- LN + l2-normalize + D^-0.5 (merged both directions) ----------------
__device__ __forceinline__ float breduce256(float v, float* red) {
    #pragma unroll
    for (int o = 16; o > 0; o >>= 1) v += __shfl_xor_sync(0xffffffffu, v, o);
    int tid = threadIdx.x;
    if ((tid & 31) == 0) red[tid >> 5] = v;
    __syncthreads();
    float t = 0.f;
    #pragma unroll
    for (int i = 0; i < 8; i++) t += red[i];
    __syncthreads();
    return t;
}

__global__ void ln_l2_kernel(const float* __restrict__ g0, const float* __restrict__ b0,
                             const float* __restrict__ g1, const float* __restrict__ b1) {
    __shared__ float red[8];
    int which = blockIdx.y;
    const float* g = which ? g1 : g0;
    const float* b = which ? b1 : b0;
    int row = blockIdx.x;
    int tid = threadIdx.x;
    const float* y = g_proj[which] + (size_t)row * NHID;
    float v[4], sum = 0.f;
    #pragma unroll
    for (int i=0;i<4;i++){ v[i] = y[tid + i*256]; sum += v[i]; }
    sum = breduce256(sum, red);
    float mu = sum * (1.f/NHID);
    float sq = 0.f;
    #pragma unroll
    for (int i=0;i<4;i++){ float d = v[i]-mu; sq += d*d; }
    sq = breduce256(sq, red);
    float rstd = rsqrtf(sq*(1.f/NHID) + 1e-5f);
    float ln[4], s2 = 0.f;
    #pragma unroll
    for (int i=0;i<4;i++){ int n = tid+i*256; ln[i] = (v[i]-mu)*rstd*g[n] + b[n]; s2 += ln[i]*ln[i]; }
    s2 = breduce256(s2, red);
    float scale = 0.125f / fmaxf(sqrtf(s2), 1e-12f);
    int bb = row >> 9, s = row & 511;
    float* outp = g_c[which];
    #pragma unroll
    for (int i=0;i<4;i++){
        int n = tid + i*256;
        int h = n >> 6, d = n & 63;
        outp[(((size_t)(bb*NH + h))*NS + s)*ND + d] = ln[i]*scale;
    }
}

// ============ per-head QKV projection — R12 proven (persistent A frags) ============
#define QPA 68
__global__ void qkv_tf32_kernel(const float* __restrict__ w_i2t, const float* __restrict__ b_i2t,
                                const float* __restrict__ w_t2i, const float* __restrict__ b_t2i) {
    extern __shared__ __align__(16) float sm[];
    float* Xq  = sm;
    float* Xkv = sm + 64*QPA;
    float* Wsm = sm + 2*64*QPA;
    int which = blockIdx.z;
    const float* in_w = which ? w_t2i : w_i2t;
    const float* in_b = which ? b_t2i : b_i2t;
    int bh = blockIdx.y;
    int h = bh & (NH-1);
    int s0 = blockIdx.x * 64;
    int tid = threadIdx.x;
    int wid = tid >> 5, lane = tid & 31;
    int wm = wid >> 1, wn = wid & 1;
    int g = lane >> 2, t = lane & 3;
    int fr0 = wm*16 + g;
    int lr = tid >> 4;
    int lc = (tid & 15) * 4;
    const float* qbase  = g_c[which]   + ((size_t)bh*NS + s0)*ND;
    const float* kvbase = g_c[which^1] + ((size_t)bh*NS + s0)*ND;
    #pragma unroll
    for (int i = 0; i < 4; i++) {
        int r = lr + i*16;
        float4 a  = *(const float4*)(qbase  + r*ND + lc);
        float4 kv = *(const float4*)(kvbase + r*ND + lc);
        float* qd = Xq + r*QPA + lc;
        float* kd = Xkv + r*QPA + lc;
        qd[0]=tf32f(a.x);  qd[1]=tf32f(a.y);  qd[2]=tf32f(a.z);  qd[3]=tf32f(a.w);
        kd[0]=tf32f(kv.x); kd[1]=tf32f(kv.y); kd[2]=tf32f(kv.z); kd[3]=tf32f(kv.w);
    }
    __syncthreads();
    unsigned aq[8][4], akv[8][4];
    #pragma unroll
    for (int kc = 0; kc < 8; kc++) {
        const float* qb = Xq  + fr0*QPA + kc*8 + t;
        const float* kb = Xkv + fr0*QPA + kc*8 + t;
        aq[kc][0]=__float_as_uint(qb[0]);   aq[kc][1]=__float_as_uint(qb[8*QPA]);
        aq[kc][2]=__float_as_uint(qb[4]);   aq[kc][3]=__float_as_uint(qb[8*QPA+4]);
        akv[kc][0]=__float_as_uint(kb[0]);  akv[kc][1]=__float_as_uint(kb[8*QPA]);
        akv[kc][2]=__float_as_uint(kb[4]);  akv[kc][3]=__float_as_uint(kb[8*QPA+4]);
    }
    for (int p = 0; p < 3; p++) {
        if (p) __syncthreads();
        const float* wsrc = in_w + ((size_t)h*192 + p*64)*64;
        #pragma unroll
        for (int i = 0; i < 4; i++) {
            int r = lr + i*16;
            float4 w = *(const float4*)(wsrc + r*64 + lc);
            float* wd = Wsm + r*QPA + lc;
            wd[0]=tf32f(w.x); wd[1]=tf32f(w.y); wd[2]=tf32f(w.z); wd[3]=tf32f(w.w);
        }
        __syncthreads();
        float acc[4][4] = {};
        #pragma unroll
        for (int kc = 0; kc < 8; kc++) {
            const unsigned* a = (p == 0) ? aq[kc] : akv[kc];
            #pragma unroll
            for (int nt = 0; nt < 4; nt++) {
                const float* bb = Wsm + (wn*32 + nt*8 + g)*QPA + kc*8 + t;
                mma_tf32(acc[nt], a, __float_as_uint(bb[0]), __float_as_uint(bb[4]));
            }
        }
        float* dst = (p==0) ? g_q[which] : (p==1) ? g_k[which] : g_v[which];
        float qscale = (p==0) ? 0.125f : 1.f;
        const float* bsrc = in_b + h*192 + p*64;
        #pragma unroll
        for (int nt = 0; nt < 4; nt++) {
            int c = wn*32 + nt*8 + 2*t;
            float bx = bsrc[c], by = bsrc[c+1];
            float* o0 = dst + ((size_t)bh*NS + s0 + fr0)*ND + c;
            float* o1 = dst + ((size_t)bh*NS + s0 + fr0 + 8)*ND + c;
            *(float2*)o0 = make_float2((acc[nt][0]+bx)*qscale, (acc[nt][1]+by)*qscale);
            *(float2*)o1 = make_float2((acc[nt][2]+bx)*qscale, (acc[nt][3]+by)*qscale);
        }
    }
}

// ============ flash attention v2 — R12 proven ============
#define KPAD 68   // scalar K frag loads (4g+t) conflict-free
#define VPAD 72   // scalar V loads (8t+g) conflict-free
__global__ void __launch_bounds__(256, 2) attn_kernel() {
    __shared__ __align__(16) float ks[64*KPAD];
    __shared__ __align__(16) float vs[64*VPAD];
    int which = blockIdx.z;
    const float* Q = g_q[which];
    const float* K = g_k[which];
    const float* V = g_v[which];
    float* O = g_o[which];
    int bh = blockIdx.y;
    int q0 = blockIdx.x * 128;
    int tid = threadIdx.x, wid = tid >> 5, lane = tid & 31;
    int g = lane >> 2, t = lane & 3;

    // ---- stage Q (128 x 64, tf32) into ks(rows 0-63) / vs(rows 64-127) ----
    {
        int r = tid >> 1;
        int c0 = (tid & 1) * 32;
        const float* src = Q + ((size_t)bh*NS + q0 + r)*ND + c0;
        float* dst = (r < 64) ? (ks + r*KPAD + c0) : (vs + (r-64)*VPAD + c0);
        #pragma unroll
        for (int i = 0; i < 8; i++) {
            float4 v4 = *(const float4*)(src + i*4);
            dst[i*4+0]=tf32f(v4.x); dst[i*4+1]=tf32f(v4.y);
            dst[i*4+2]=tf32f(v4.z); dst[i*4+3]=tf32f(v4.w);
        }
    }
    __syncthreads();
    unsigned qf[8][4];
    {
        int rq = wid*16 + g;
        const float* base = (rq < 64) ? (ks + rq*KPAD) : (vs + (rq-64)*VPAD);
        int stride = (rq < 64) ? KPAD : VPAD;
        #pragma unroll
        for (int kc = 0; kc < 8; kc++) {
            qf[kc][0] = __float_as_uint(base[kc*8 + t]);
            qf[kc][1] = __float_as_uint(base[8*stride + kc*8 + t]);
            qf[kc][2] = __float_as_uint(base[kc*8 + t + 4]);
            qf[kc][3] = __float_as_uint(base[8*stride + kc*8 + t + 4]);
        }
    }
    __syncthreads();

    float of[8][4] = {};
    float m0 = -1e30f, m1 = -1e30f, l0 = 0.f, l1 = 0.f;

    for (int j0 = 0; j0 < NS; j0 += 64) {
        // ---- stage K,V tile (64 x 64 each, tf32) ----
        {
            int r = tid >> 2, c0 = (tid & 3) * 16;
            const float* ksrc = K + ((size_t)bh*NS + j0 + r)*ND + c0;
            const float* vsrc = V + ((size_t)bh*NS + j0 + r)*ND + c0;
            float* kd = ks + r*KPAD + c0;
            float* vd = vs + r*VPAD + c0;
            #pragma unroll
            for (int i = 0; i < 4; i++) {
                float4 kv = *(const float4*)(ksrc + i*4);
                float4 vv = *(const float4*)(vsrc + i*4);
                kd[i*4+0]=tf32f(kv.x); kd[i*4+1]=tf32f(kv.y);
                kd[i*4+2]=tf32f(kv.z); kd[i*4+3]=tf32f(kv.w);
                vd[i*4+0]=tf32f(vv.x); vd[i*4+1]=tf32f(vv.y);
                vd[i*4+2]=tf32f(vv.z); vd[i*4+3]=tf32f(vv.w);
            }
        }
        __syncthreads();

        // ---- S = Q @ K^T ----
        float s[8][4] = {};
        #pragma unroll
        for (int nt = 0; nt < 8; nt++) {
            const float* bb = ks + (nt*8 + g)*KPAD;
            #pragma unroll
            for (int kc = 0; kc < 8; kc++) {
                unsigned b0 = __float_as_uint(bb[kc*8 + t]);
                unsigned b1 = __float_as_uint(bb[kc*8 + t + 4]);
                mma_tf32(s[nt], qf[kc], b0, b1);
            }
        }

        // ---- register online softmax ----
        float mx0 = -1e30f, mx1 = -1e30f;
        #pragma unroll
        for (int nt = 0; nt < 8; nt++) {
            mx0 = fmaxf(mx0, fmaxf(s[nt][0], s[nt][1]));
            mx1 = fmaxf(mx1, fmaxf(s[nt][2], s[nt][3]));
        }
        mx0 = fmaxf(mx0, __shfl_xor_sync(0xffffffffu, mx0, 1));
        mx0 = fmaxf(mx0, __shfl_xor_sync(0xffffffffu, mx0, 2));
        mx1 = fmaxf(mx1, __shfl_xor_sync(0xffffffffu, mx1, 1));
        mx1 = fmaxf(mx1, __shfl_xor_sync(0xffffffffu, mx1, 2));
        float mn0 = fmaxf(m0, mx0), mn1 = fmaxf(m1, mx1);
        float f0 = __expf(m0 - mn0), f1 = __expf(m1 - mn1);
        float sum0 = 0.f, sum1 = 0.f;
        #pragma unroll
        for (int nt = 0; nt < 8; nt++) {
            float e0 = __expf(s[nt][0] - mn0);
            float e1 = __expf(s[nt][1] - mn0);
            float e2 = __expf(s[nt][2] - mn1);
            float e3 = __expf(s[nt][3] - mn1);
            sum0 += e0 + e1; sum1 += e2 + e3;
            s[nt][0] = tf32f(e0); s[nt][1] = tf32f(e1);
            s[nt][2] = tf32f(e2); s[nt][3] = tf32f(e3);
        }
        sum0 += __shfl_xor_sync(0xffffffffu, sum0, 1);
        sum0 += __shfl_xor_sync(0xffffffffu, sum0, 2);
        sum1 += __shfl_xor_sync(0xffffffffu, sum1, 1);
        sum1 += __shfl_xor_sync(0xffffffffu, sum1, 2);
        l0 = l0*f0 + sum0; l1 = l1*f1 + sum1;
        m0 = mn0; m1 = mn1;
        #pragma unroll
        for (int nt = 0; nt < 8; nt++) {
            of[nt][0] *= f0; of[nt][1] *= f0;
            of[nt][2] *= f1; of[nt][3] *= f1;
        }

        // ---- O += P @ V ----
        int src0 = (lane & ~3) | (t >> 1);
        int src1 = src0 + 2;
        bool odd = (t & 1);
        #pragma unroll
        for (int kc = 0; kc < 8; kc++) {
            float v00 = __shfl_sync(0xffffffffu, s[kc][0], src0);
            float v01 = __shfl_sync(0xffffffffu, s[kc][1], src0);
            float v10 = __shfl_sync(0xffffffffu, s[kc][2], src0);
            float v11 = __shfl_sync(0xffffffffu, s[kc][3], src0);
            float w00 = __shfl_sync(0xffffffffu, s[kc][0], src1);
            float w01 = __shfl_sync(0xffffffffu, s[kc][1], src1);
            float w10 = __shfl_sync(0xffffffffu, s[kc][2], src1);
            float w11 = __shfl_sync(0xffffffffu, s[kc][3], src1);
            unsigned a[4];
            a[0] = __float_as_uint(odd ? v01 : v00);
            a[1] = __float_as_uint(odd ? v11 : v10);
            a[2] = __float_as_uint(odd ? w01 : w00);
            a[3] = __float_as_uint(odd ? w11 : w10);
            const float* vb0 = vs + (kc*8 + t)*VPAD + g;
            const float* vb1 = vs + (kc*8 + t + 4)*VPAD + g;
            #pragma unroll
            for (int nt = 0; nt < 8; nt++) {
                unsigned b0 = __float_as_uint(vb0[nt*8]);
                unsigned b1 = __float_as_uint(vb1[nt*8]);
                mma_tf32(of[nt], a, b0, b1);
            }
        }
        __syncthreads();
    }

    // ---- epilogue ----
    float il0 = 1.f / l0, il1 = 1.f / l1;
    int r0 = wid*16 + g;
    #pragma unroll
    for (int nt = 0; nt < 8; nt++) {
        int c = nt*8 + 2*t;
        float* o0 = O + ((size_t)bh*NS + q0 + r0)*ND + c;
        float* o1 = o0 + 8*ND;
        *(float2*)o0 = make_float2(of[nt][0]*il0, of[nt][1]*il0);
        *(float2*)o1 = make_float2(of[nt][2]*il1, of[nt][3]*il1);
    }
}

// ============ fused out-projection (both dirs) + residual + final LN ============
// R12-style scalar fragment addressing; smem: 4 tiles of 64*QPA, comb overlays first two.
#define CSTR 132
__global__ void outproj_ln_kernel(const float* __restrict__ w0, const float* __restrict__ bw0,
                                  const float* __restrict__ w1, const float* __restrict__ bw1,
                                  const float* __restrict__ hg, const float* __restrict__ hb,
                                  float* __restrict__ out) {
    extern __shared__ __align__(16) float sm[];
    float* Xs0 = sm;
    float* Ws0 = sm + 64*QPA;
    float* Xs1 = sm + 2*64*QPA;
    float* Ws1 = sm + 3*64*QPA;
    float* comb = sm;                // 64*CSTR = 8448 floats <= 2*64*68 = 8704
    int bh = blockIdx.y, h = bh & (NH-1), s0 = blockIdx.x*64;
    int tid = threadIdx.x;
    int wid = tid >> 5, lane = tid & 31;
    int wm = wid >> 1, wn = wid & 1;
    int g = lane >> 2, t = lane & 3;
    int fr0 = wm*16 + g;
    int lr = tid >> 4, lc = (tid & 15) * 4;
    const float* x0 = g_o[0] + ((size_t)bh*NS + s0)*ND;
    const float* x1 = g_o[1] + ((size_t)bh*NS + s0)*ND;
    const float* ws0 = w0 + (size_t)h*64*64;
    const float* ws1 = w1 + (size_t)h*64*64;
    #pragma unroll
    for (int i = 0; i < 4; i++) {
        int r = lr + i*16;
        float4 a0 = *(const float4*)(x0  + r*ND + lc);
        float4 a1 = *(const float4*)(x1  + r*ND + lc);
        float4 v0 = *(const float4*)(ws0 + r*64 + lc);
        float4 v1 = *(const float4*)(ws1 + r*64 + lc);
        float* d;
        d = Xs0 + r*QPA + lc; d[0]=tf32f(a0.x); d[1]=tf32f(a0.y); d[2]=tf32f(a0.z); d[3]=tf32f(a0.w);
        d = Ws0 + r*QPA + lc; d[0]=tf32f(v0.x); d[1]=tf32f(v0.y); d[2]=tf32f(v0.z); d[3]=tf32f(v0.w);
        d = Xs1 + r*QPA + lc; d[0]=tf32f(a1.x); d[1]=tf32f(a1.y); d[2]=tf32f(a1.z); d[3]=tf32f(a1.w);
        d = Ws1 + r*QPA + lc; d[0]=tf32f(v1.x); d[1]=tf32f(v1.y); d[2]=tf32f(v1.z); d[3]=tf32f(v1.w);
    }
    __syncthreads();
    float acc0[4][4] = {}, acc1[4][4] = {};
    #pragma unroll
    for (int kc = 0; kc < 8; kc++) {
        const float* ab0 = Xs0 + fr0*QPA + kc*8 + t;
        const float* ab1 = Xs1 + fr0*QPA + kc*8 + t;
        unsigned a0[4], a1[4];
        a0[0]=__float_as_uint(ab0[0]);        a0[1]=__float_as_uint(ab0[8*QPA]);
        a0[2]=__float_as_uint(ab0[4]);        a0[3]=__float_as_uint(ab0[8*QPA+4]);
        a1[0]=__float_as_uint(ab1[0]);        a1[1]=__float_as_uint(ab1[8*QPA]);
        a1[2]=__float_as_uint(ab1[4]);        a1[3]=__float_as_uint(ab1[8*QPA+4]);
        #pragma unroll
        for (int nt = 0; nt < 4; nt++) {
            const float* bb0 = Ws0 + (wn*32 + nt*8 + g)*QPA + kc*8 + t;
            const float* bb1 = Ws1 + (wn*32 + nt*8 + g)*QPA + kc*8 + t;
            mma_tf32(acc0[nt], a0, __float_as_uint(bb0[0]), __float_as_uint(bb0[4]));
            mma_tf32(acc1[nt], a1, __float_as_uint(bb1[0]), __float_as_uint(bb1[4]));
        }
    }
    __syncthreads();   // all smem reads done; comb overlays Xs0/Ws0
    const float* r0p = g_c[0] + ((size_t)bh*NS + s0)*ND;
    const float* r1p = g_c[1] + ((size_t)bh*NS + s0)*ND;
    #pragma unroll
    for (int nt = 0; nt < 4; nt++) {
        int c = wn*32 + nt*8 + 2*t;
        float b0x = bw0[h*64+c], b0y = bw0[h*64+c+1];
        float b1x = bw1[h*64+c], b1y = bw1[h*64+c+1];
        int ra = fr0, rb = fr0 + 8;
        float2 ra0 = *(const float2*)(r0p + ra*ND + c);
        float2 rb0 = *(const float2*)(r0p + rb*ND + c);
        float2 ra1 = *(const float2*)(r1p + ra*ND + c);
        float2 rb1 = *(const float2*)(r1p + rb*ND + c);
        *(float2*)(comb + ra*CSTR + c)      = make_float2(acc0[nt][0]+b0x+ra0.x, acc0[nt][1]+b0y+ra0.y);
        *(float2*)(comb + rb*CSTR + c)      = make_float2(acc0[nt][2]+b0x+rb0.x, acc0[nt][3]+b0y+rb0.y);
        *(float2*)(comb + ra*CSTR + 64 + c) = make_float2(acc1[nt][0]+b1x+ra1.x, acc1[nt][1]+b1y+ra1.y);
        *(float2*)(comb + rb*CSTR + 64 + c) = make_float2(acc1[nt][2]+b1x+rb1.x, acc1[nt][3]+b1y+rb1.y);
    }
    __syncthreads();
    // LayerNorm over 128: 4 threads per row
    {
        int r = tid >> 2, q = tid & 3;
        const float* prow = comb + r*CSTR + q*32;
        float v[32];
        float sum = 0.f;
        #pragma unroll
        for (int i = 0; i < 8; i++) {
            float4 v4 = *(const float4*)(prow + i*4);
            v[i*4+0]=v4.x; v[i*4+1]=v4.y; v[i*4+2]=v4.z; v[i*4+3]=v4.w;
            sum += v4.x + v4.y + v4.z + v4.w;
        }
        sum += __shfl_xor_sync(0xffffffffu, sum, 1);
        sum += __shfl_xor_sync(0xffffffffu, sum, 2);
        float mu = sum * (1.f/128.f);
        float sq = 0.f;
        #pragma unroll
        for (int i = 0; i < 32; i++) { float d = v[i]-mu; sq += d*d; }
        sq += __shfl_xor_sync(0xffffffffu, sq, 1);
        sq += __shfl_xor_sync(0xffffffffu, sq, 2);
        float rstd = rsqrtf(sq*(1.f/128.f) + 1e-5f);
        float* orow = out + ((size_t)bh*NS + s0 + r)*128 + q*32;
        const float* gg = hg + h*128 + q*32;
        const float* bb = hb + h*128 + q*32;
        #pragma unroll
        for (int i = 0; i < 8; i++) {
            float4 g4 = *(const float4*)(gg + i*4);
            float4 b4 = *(const float4*)(bb + i*4);
            float4 o4;
            o4.x = (v[i*4+0]-mu)*rstd*g4.x + b4.x;
            o4.y = (v[i*4+1]-mu)*rstd*g4.y + b4.y;
            o4.z = (v[i*4+2]-mu)*rstd*g4.z + b4.z;
            o4.w = (v[i*4+3]-mu)*rstd*g4.w + b4.w;
            *(float4*)(orow + i*4) = o4;
        }
    }
}

// ---------------- launch ----------------
extern "C" void kernel_launch(void* const* d_in, const int* in_sizes, int n_in,
                              void* d_out, int out_size) {
    const float* image     = (const float*)d_in[0];
    const float* text      = (const float*)d_in[1];
    const float* img_w     = (const float*)d_in[2];
    const float* img_b     = (const float*)d_in[3];
    const float* img_g     = (const float*)d_in[4];
    const float* img_lb    = (const float*)d_in[5];
    const float* txt_w     = (const float*)d_in[6];
    const float* txt_b     = (const float*)d_in[7];
    const float* txt_g     = (const float*)d_in[8];
    const float* txt_lb    = (const float*)d_in[9];
    const float* i2t_in_w  = (const float*)d_in[10];
    const float* i2t_in_b  = (const float*)d_in[11];
    const float* i2t_out_w = (const float*)d_in[12];
    const float* i2t_out_b = (const float*)d_in[13];
    const float* t2i_in_w  = (const float*)d_in[14];
    const float* t2i_in_b  = (const float*)d_in[15];
    const float* t2i_out_w = (const float*)d_in[16];
    const float* t2i_out_b = (const float*)d_in[17];
    const float* hn_g      = (const float*)d_in[18];
    const float* hn_b      = (const float*)d_in[19];
    float* out = (float*)d_out;

    const int QKV_SMEM = 3*64*QPA*4;   // 52224 B
    const int OPL_SMEM = 4*64*QPA*4;   // 69632 B
    static int attrs_set = 0;
    if (!attrs_set) {
        cudaFuncSetAttribute(qkv_tf32_kernel, cudaFuncAttributeMaxDynamicSharedMemorySize, QKV_SMEM);
        cudaFuncSetAttribute(outproj_ln_kernel, cudaFuncAttributeMaxDynamicSharedMemorySize, OPL_SMEM);
        attrs_set = 1;
    }

    dim3 thr(256);
    gemm_tf32_kernel<<<dim3(8,64), thr>>>(image, img_w, img_b, 768, 0);
    gemm_tf32_kernel<<<dim3(8,64), thr>>>(text,  txt_w, txt_b, 512, 1);
    ln_l2_kernel<<<dim3(8192,2), thr>>>(img_g, img_lb, txt_g, txt_lb);
    qkv_tf32_kernel<<<dim3(8,256,2), thr, QKV_SMEM>>>(i2t_in_w, i2t_in_b, t2i_in_w, t2i_in_b);
    attn_kernel<<<dim3(4,256,2), thr>>>();
    outproj_ln_kernel<<<dim3(8,256), thr, OPL_SMEM>>>(i2t_out_w, i2t_out_b, t2i_out_w, t2i_out_b,
                                                      hn_g, hn_b, out);
}

// round 17
// speedup vs baseline: 1.2938x; 1.0843x over previous
#include <cuda_runtime.h>
#include <math.h>

#define NB 16
#define NS 512
#define NH 16
#define ND 64
#define NHID 1024
#define NROW (NB*NS)        // 8192
#define NBH (NB*NH)         // 256
#define NTOK (NBH*NS*ND)    // 8388608

// ---------------- scratch ----------------
__device__ __align__(16) float g_proj[2][NROW*NHID];
__device__ __align__(16) float g_c[2][NTOK];           // (B,H,S,D)
__device__ __align__(16) float g_q[2][NTOK];           // tf32-rounded
__device__ __align__(16) float g_k[2][NTOK];           // tf32-rounded
__device__ __align__(16) float g_v[2][NTOK];           // tf32-rounded
__device__ __align__(16) float g_o[2][NTOK];
__device__ __align__(16) float g_comb[NBH*NS*2*ND];    // (B,H,S,128)

// ---------------- tf32 mma helpers ----------------
__device__ __forceinline__ unsigned cvt_tf32(float x) {
    unsigned u; asm("cvt.rna.tf32.f32 %0, %1;" : "=r"(u) : "f"(x)); return u;
}
__device__ __forceinline__ float tf32f(float x) {
    return __uint_as_float(cvt_tf32(x));
}
__device__ __forceinline__ void mma_tf32(float c[4], const unsigned a[4], unsigned b0, unsigned b1) {
    asm("mma.sync.aligned.m16n8k8.row.col.f32.tf32.tf32.f32 "
        "{%0,%1,%2,%3}, {%4,%5,%6,%7}, {%8,%9}, {%0,%1,%2,%3};"
        : "+f"(c[0]), "+f"(c[1]), "+f"(c[2]), "+f"(c[3])
        : "r"(a[0]), "r"(a[1]), "r"(a[2]), "r"(a[3]), "r"(b0), "r"(b1));
}
// ---------------- cp.async helpers ----------------
__device__ __forceinline__ void cpa16(void* s, const void* g) {
    unsigned sa = (unsigned)__cvta_generic_to_shared(s);
    asm volatile("cp.async.ca.shared.global [%0], [%1], 16;" :: "r"(sa), "l"(g));
}
#define CP_COMMIT() asm volatile("cp.async.commit_group;")
#define CP_WAIT0()  asm volatile("cp.async.wait_group 0;")

// ============ big projection GEMM (tf32 tensor cores) — R12 proven ============
#define GPA 36
__global__ void gemm_tf32_kernel(const float* __restrict__ A,
                                 const float* __restrict__ W,
                                 const float* __restrict__ bias,
                                 int K, int which) {
    __shared__ __align__(16) float As[128*GPA];
    __shared__ __align__(16) float Ws[128*GPA];
    float* C = g_proj[which];
    int tid = threadIdx.x;
    int wid = tid >> 5, lane = tid & 31;
    int wm = wid >> 1, wn = wid & 1;
    int g = lane >> 2, t = lane & 3;
    int m0 = blockIdx.y * 128, n0 = blockIdx.x * 128;
    int lr = tid >> 3;
    int lc = (tid & 7) * 4;
    float acc[2][8][4] = {};
    for (int k0 = 0; k0 < K; k0 += 32) {
        #pragma unroll
        for (int i = 0; i < 4; i++) {
            int r = lr + i*32;
            float4 av = *(const float4*)(A + (size_t)(m0 + r)*K + k0 + lc);
            float4 wv = *(const float4*)(W + (size_t)(n0 + r)*K + k0 + lc);
            float* ad = As + r*GPA + lc;
            float* wd = Ws + r*GPA + lc;
            ad[0]=tf32f(av.x); ad[1]=tf32f(av.y); ad[2]=tf32f(av.z); ad[3]=tf32f(av.w);
            wd[0]=tf32f(wv.x); wd[1]=tf32f(wv.y); wd[2]=tf32f(wv.z); wd[3]=tf32f(wv.w);
        }
        __syncthreads();
        #pragma unroll
        for (int kc = 0; kc < 4; kc++) {
            unsigned a[2][4];
            #pragma unroll
            for (int mf = 0; mf < 2; mf++) {
                const float* ab = As + (wm*32 + mf*16 + g)*GPA + kc*8 + t;
                a[mf][0] = __float_as_uint(ab[0]);
                a[mf][1] = __float_as_uint(ab[8*GPA]);
                a[mf][2] = __float_as_uint(ab[4]);
                a[mf][3] = __float_as_uint(ab[8*GPA+4]);
            }
            #pragma unroll
            for (int nf = 0; nf < 8; nf++) {
                const float* bb = Ws + (wn*64 + nf*8 + g)*GPA + kc*8 + t;
                unsigned b0 = __float_as_uint(bb[0]);
                unsigned b1 = __float_as_uint(bb[4]);
                mma_tf32(acc[0][nf], a[0], b0, b1);
                mma_tf32(acc[1][nf], a[1], b0, b1);
            }
        }
        __syncthreads();
    }
    #pragma unroll
    for (int mf = 0; mf < 2; mf++) {
        int r0 = m0 + wm*32 + mf*16 + g;
        #pragma unroll
        for (int nf = 0; nf < 8; nf++) {
            int c = n0 + wn*64 + nf*8 + 2*t;
            float bx = bias[c], by = bias[c+1];
            *(float2*)(C + (size_t)r0*NHID + c) =
                make_float2(acc[mf][nf][0] + bx, acc[mf][nf][1] + by);
            *(float2*)(C + (size_t)(r0+8)*NHID + c) =
                make_float2(acc[mf][nf][2] + bx, acc[mf][nf][3] + by);
        }
    }
}

// ---------------- LN + l2-normalize + D^-0.5 (merged both directions) ----------------
__device__ __forceinline__ float breduce256(float v, float* red) {
    #pragma unroll
    for (int o = 16; o > 0; o >>= 1) v += __shfl_xor_sync(0xffffffffu, v, o);
    int tid = threadIdx.x;
    if ((tid & 31) == 0) red[tid >> 5] = v;
    __syncthreads();
    float t = 0.f;
    #pragma unroll
    for (int i = 0; i < 8; i++) t += red[i];
    __syncthreads();
    return t;
}

__global__ void ln_l2_kernel(const float* __restrict__ g0, const float* __restrict__ b0,
                             const float* __restrict__ g1, const float* __restrict__ b1) {
    __shared__ float red[8];
    int which = blockIdx.y;
    const float* g = which ? g1 : g0;
    const float* b = which ? b1 : b0;
    int row = blockIdx.x;
    int tid = threadIdx.x;
    const float* y = g_proj[which] + (size_t)row * NHID;
    float v[4], sum = 0.f;
    #pragma unroll
    for (int i=0;i<4;i++){ v[i] = y[tid + i*256]; sum += v[i]; }
    sum = breduce256(sum, red);
    float mu = sum * (1.f/NHID);
    float sq = 0.f;
    #pragma unroll
    for (int i=0;i<4;i++){ float d = v[i]-mu; sq += d*d; }
    sq = breduce256(sq, red);
    float rstd = rsqrtf(sq*(1.f/NHID) + 1e-5f);
    float ln[4], s2 = 0.f;
    #pragma unroll
    for (int i=0;i<4;i++){ int n = tid+i*256; ln[i] = (v[i]-mu)*rstd*g[n] + b[n]; s2 += ln[i]*ln[i]; }
    s2 = breduce256(s2, red);
    float scale = 0.125f / fmaxf(sqrtf(s2), 1e-12f);
    int bb = row >> 9, s = row & 511;
    float* outp = g_c[which];
    #pragma unroll
    for (int i=0;i<4;i++){
        int n = tid + i*256;
        int h = n >> 6, d = n & 63;
        outp[(((size_t)(bb*NH + h))*NS + s)*ND + d] = ln[i]*scale;
    }
}

// ============ per-head QKV projection — scalar frags, no persistent regs ============
#define QPA 68
__global__ void __launch_bounds__(256, 3)
qkv_tf32_kernel(const float* __restrict__ w_i2t, const float* __restrict__ b_i2t,
                const float* __restrict__ w_t2i, const float* __restrict__ b_t2i) {
    extern __shared__ __align__(16) float sm[];
    float* Xq  = sm;
    float* Xkv = sm + 64*QPA;
    float* Wsm = sm + 2*64*QPA;
    int which = blockIdx.z;
    const float* in_w = which ? w_t2i : w_i2t;
    const float* in_b = which ? b_t2i : b_i2t;
    int bh = blockIdx.y;
    int h = bh & (NH-1);
    int s0 = blockIdx.x * 64;
    int tid = threadIdx.x;
    int wid = tid >> 5, lane = tid & 31;
    int wm = wid >> 1, wn = wid & 1;
    int g = lane >> 2, t = lane & 3;
    int fr0 = wm*16 + g;
    int lr = tid >> 4;
    int lc = (tid & 15) * 4;
    const float* qbase  = g_c[which]   + ((size_t)bh*NS + s0)*ND;
    const float* kvbase = g_c[which^1] + ((size_t)bh*NS + s0)*ND;
    #pragma unroll
    for (int i = 0; i < 4; i++) {
        int r = lr + i*16;
        float4 a  = *(const float4*)(qbase  + r*ND + lc);
        float4 kv = *(const float4*)(kvbase + r*ND + lc);
        float* qd = Xq + r*QPA + lc;
        float* kd = Xkv + r*QPA + lc;
        qd[0]=tf32f(a.x);  qd[1]=tf32f(a.y);  qd[2]=tf32f(a.z);  qd[3]=tf32f(a.w);
        kd[0]=tf32f(kv.x); kd[1]=tf32f(kv.y); kd[2]=tf32f(kv.z); kd[3]=tf32f(kv.w);
    }
    for (int p = 0; p < 3; p++) {
        __syncthreads();   // X staged (p=0) / Wsm reads of prior p done (p>0)
        const float* wsrc = in_w + ((size_t)h*192 + p*64)*64;
        #pragma unroll
        for (int i = 0; i < 4; i++) {
            int r = lr + i*16;
            float4 w = *(const float4*)(wsrc + r*64 + lc);
            float* wd = Wsm + r*QPA + lc;
            wd[0]=tf32f(w.x); wd[1]=tf32f(w.y); wd[2]=tf32f(w.z); wd[3]=tf32f(w.w);
        }
        __syncthreads();
        const float* Xs = (p == 0) ? Xq : Xkv;
        float acc[4][4] = {};
        #pragma unroll
        for (int kc = 0; kc < 8; kc++) {
            const float* ab = Xs + fr0*QPA + kc*8 + t;
            unsigned a[4];
            a[0] = __float_as_uint(ab[0]);
            a[1] = __float_as_uint(ab[8*QPA]);
            a[2] = __float_as_uint(ab[4]);
            a[3] = __float_as_uint(ab[8*QPA+4]);
            #pragma unroll
            for (int nt = 0; nt < 4; nt++) {
                const float* bb = Wsm + (wn*32 + nt*8 + g)*QPA + kc*8 + t;
                mma_tf32(acc[nt], a, __float_as_uint(bb[0]), __float_as_uint(bb[4]));
            }
        }
        float* dst = (p==0) ? g_q[which] : (p==1) ? g_k[which] : g_v[which];
        float qscale = (p==0) ? 0.125f : 1.f;
        const float* bsrc = in_b + h*192 + p*64;
        #pragma unroll
        for (int nt = 0; nt < 4; nt++) {
            int c = wn*32 + nt*8 + 2*t;
            float bx = bsrc[c], by = bsrc[c+1];
            float* o0 = dst + ((size_t)bh*NS + s0 + fr0)*ND + c;
            float* o1 = dst + ((size_t)bh*NS + s0 + fr0 + 8)*ND + c;
            // pre-round to tf32 so attention can raw-copy (bit-identical to rounding there)
            *(float2*)o0 = make_float2(tf32f((acc[nt][0]+bx)*qscale), tf32f((acc[nt][1]+by)*qscale));
            *(float2*)o1 = make_float2(tf32f((acc[nt][2]+bx)*qscale), tf32f((acc[nt][3]+by)*qscale));
        }
    }
}

// ============ flash attention: cp.async double-buffered K/V, pre-rounded inputs ============
#define KPAD 68   // scalar K frag loads (4g+t) conflict-free
#define VPAD 72   // scalar V loads (8t+g) conflict-free
#define TILE_F (64*KPAD + 64*VPAD)   // 8960 floats per buffer
__global__ void __launch_bounds__(256, 2) attn_kernel() {
    extern __shared__ __align__(16) float smx[];
    int which = blockIdx.z;
    const float* Q = g_q[which];
    const float* K = g_k[which];
    const float* V = g_v[which];
    float* O = g_o[which];
    int bh = blockIdx.y;
    int q0 = blockIdx.x * 128;
    int tid = threadIdx.x, wid = tid >> 5, lane = tid & 31;
    int g = lane >> 2, t = lane & 3;

    // ---- stage Q (128 x 64, already tf32) into buffer 0 ----
    {
        int r = tid >> 1;
        int c0 = (tid & 1) * 32;
        const float* src = Q + ((size_t)bh*NS + q0 + r)*ND + c0;
        float* dst = (r < 64) ? (smx + r*KPAD + c0) : (smx + 64*KPAD + (r-64)*VPAD + c0);
        #pragma unroll
        for (int i = 0; i < 8; i++)
            *(float4*)(dst + i*4) = *(const float4*)(src + i*4);
    }
    __syncthreads();
    unsigned qf[8][4];
    {
        int rq = wid*16 + g;
        const float* base = (rq < 64) ? (smx + rq*KPAD) : (smx + 64*KPAD + (rq-64)*VPAD);
        int stride = (rq < 64) ? KPAD : VPAD;
        #pragma unroll
        for (int kc = 0; kc < 8; kc++) {
            qf[kc][0] = __float_as_uint(base[kc*8 + t]);
            qf[kc][1] = __float_as_uint(base[8*stride + kc*8 + t]);
            qf[kc][2] = __float_as_uint(base[kc*8 + t + 4]);
            qf[kc][3] = __float_as_uint(base[8*stride + kc*8 + t + 4]);
        }
    }
    __syncthreads();

    // staging thread mapping
    int sr = tid >> 2, sc = (tid & 3) * 16;
    // ---- prefetch tile 0 into buffer 0 ----
    {
        float* kd = smx + sr*KPAD + sc;
        float* vd = smx + 64*KPAD + sr*VPAD + sc;
        const float* kg = K + ((size_t)bh*NS + 0 + sr)*ND + sc;
        const float* vg = V + ((size_t)bh*NS + 0 + sr)*ND + sc;
        #pragma unroll
        for (int i = 0; i < 4; i++) {
            cpa16(kd + i*4, kg + i*4);
            cpa16(vd + i*4, vg + i*4);
        }
        CP_COMMIT();
    }

    float of[8][4] = {};
    float m0 = -1e30f, m1 = -1e30f, l0 = 0.f, l1 = 0.f;
    int buf = 0;

    for (int j0 = 0; j0 < NS; j0 += 64) {
        CP_WAIT0();
        __syncthreads();   // current buffer ready; previous compute done
        // ---- prefetch next tile into other buffer ----
        if (j0 + 64 < NS) {
            float* kd = smx + (buf^1)*TILE_F + sr*KPAD + sc;
            float* vd = smx + (buf^1)*TILE_F + 64*KPAD + sr*VPAD + sc;
            const float* kg = K + ((size_t)bh*NS + j0 + 64 + sr)*ND + sc;
            const float* vg = V + ((size_t)bh*NS + j0 + 64 + sr)*ND + sc;
            #pragma unroll
            for (int i = 0; i < 4; i++) {
                cpa16(kd + i*4, kg + i*4);
                cpa16(vd + i*4, vg + i*4);
            }
            CP_COMMIT();
        }
        const float* ks = smx + buf*TILE_F;
        const float* vs = smx + buf*TILE_F + 64*KPAD;

        // ---- S = Q @ K^T ----
        float s[8][4] = {};
        #pragma unroll
        for (int nt = 0; nt < 8; nt++) {
            const float* bb = ks + (nt*8 + g)*KPAD;
            #pragma unroll
            for (int kc = 0; kc < 8; kc++) {
                unsigned b0 = __float_as_uint(bb[kc*8 + t]);
                unsigned b1 = __float_as_uint(bb[kc*8 + t + 4]);
                mma_tf32(s[nt], qf[kc], b0, b1);
            }
        }

        // ---- register online softmax ----
        float mx0 = -1e30f, mx1 = -1e30f;
        #pragma unroll
        for (int nt = 0; nt < 8; nt++) {
            mx0 = fmaxf(mx0, fmaxf(s[nt][0], s[nt][1]));
            mx1 = fmaxf(mx1, fmaxf(s[nt][2], s[nt][3]));
        }
        mx0 = fmaxf(mx0, __shfl_xor_sync(0xffffffffu, mx0, 1));
        mx0 = fmaxf(mx0, __shfl_xor_sync(0xffffffffu, mx0, 2));
        mx1 = fmaxf(mx1, __shfl_xor_sync(0xffffffffu, mx1, 1));
        mx1 = fmaxf(mx1, __shfl_xor_sync(0xffffffffu, mx1, 2));
        float mn0 = fmaxf(m0, mx0), mn1 = fmaxf(m1, mx1);
        float f0 = __expf(m0 - mn0), f1 = __expf(m1 - mn1);
        float sum0 = 0.f, sum1 = 0.f;
        #pragma unroll
        for (int nt = 0; nt < 8; nt++) {
            float e0 = __expf(s[nt][0] - mn0);
            float e1 = __expf(s[nt][1] - mn0);
            float e2 = __expf(s[nt][2] - mn1);
            float e3 = __expf(s[nt][3] - mn1);
            sum0 += e0 + e1; sum1 += e2 + e3;
            s[nt][0] = tf32f(e0); s[nt][1] = tf32f(e1);
            s[nt][2] = tf32f(e2); s[nt][3] = tf32f(e3);
        }
        sum0 += __shfl_xor_sync(0xffffffffu, sum0, 1);
        sum0 += __shfl_xor_sync(0xffffffffu, sum0, 2);
        sum1 += __shfl_xor_sync(0xffffffffu, sum1, 1);
        sum1 += __shfl_xor_sync(0xffffffffu, sum1, 2);
        l0 = l0*f0 + sum0; l1 = l1*f1 + sum1;
        m0 = mn0; m1 = mn1;
        #pragma unroll
        for (int nt = 0; nt < 8; nt++) {
            of[nt][0] *= f0; of[nt][1] *= f0;
            of[nt][2] *= f1; of[nt][3] *= f1;
        }

        // ---- O += P @ V ----
        int src0 = (lane & ~3) | (t >> 1);
        int src1 = src0 + 2;
        bool odd = (t & 1);
        #pragma unroll
        for (int kc = 0; kc < 8; kc++) {
            float v00 = __shfl_sync(0xffffffffu, s[kc][0], src0);
            float v01 = __shfl_sync(0xffffffffu, s[kc][1], src0);
            float v10 = __shfl_sync(0xffffffffu, s[kc][2], src0);
            float v11 = __shfl_sync(0xffffffffu, s[kc][3], src0);
            float w00 = __shfl_sync(0xffffffffu, s[kc][0], src1);
            float w01 = __shfl_sync(0xffffffffu, s[kc][1], src1);
            float w10 = __shfl_sync(0xffffffffu, s[kc][2], src1);
            float w11 = __shfl_sync(0xffffffffu, s[kc][3], src1);
            unsigned a[4];
            a[0] = __float_as_uint(odd ? v01 : v00);
            a[1] = __float_as_uint(odd ? v11 : v10);
            a[2] = __float_as_uint(odd ? w01 : w00);
            a[3] = __float_as_uint(odd ? w11 : w10);
            const float* vb0 = vs + (kc*8 + t)*VPAD + g;
            const float* vb1 = vs + (kc*8 + t + 4)*VPAD + g;
            #pragma unroll
            for (int nt = 0; nt < 8; nt++) {
                unsigned b0 = __float_as_uint(vb0[nt*8]);
                unsigned b1 = __float_as_uint(vb1[nt*8]);
                mma_tf32(of[nt], a, b0, b1);
            }
        }
        buf ^= 1;
    }

    // ---- epilogue ----
    float il0 = 1.f / l0, il1 = 1.f / l1;
    int r0 = wid*16 + g;
    #pragma unroll
    for (int nt = 0; nt < 8; nt++) {
        int c = nt*8 + 2*t;
        float* o0 = O + ((size_t)bh*NS + q0 + r0)*ND + c;
        float* o1 = o0 + 8*ND;
        *(float2*)o0 = make_float2(of[nt][0]*il0, of[nt][1]*il0);
        *(float2*)o1 = make_float2(of[nt][2]*il1, of[nt][3]*il1);
    }
}

// ============ out projection + residual (merged both directions) — R12 proven ============
__global__ void outproj_tf32_kernel(const float* __restrict__ w_i2t, const float* __restrict__ b_i2t,
                                    const float* __restrict__ w_t2i, const float* __restrict__ b_t2i) {
    __shared__ __align__(16) float Xs[64*QPA];
    __shared__ __align__(16) float Wsm[64*QPA];
    int which = blockIdx.z;
    const float* out_w = which ? w_t2i : w_i2t;
    const float* out_b = which ? b_t2i : b_i2t;
    int bh = blockIdx.y, h = bh & (NH-1), s0 = blockIdx.x*64;
    int tid = threadIdx.x;
    int wid = tid >> 5, lane = tid & 31;
    int wm = wid >> 1, wn = wid & 1;
    int g = lane >> 2, t = lane & 3;
    int fr0 = wm*16 + g;
    int lr = tid >> 4, lc = (tid & 15) * 4;
    const float* xbase = g_o[which] + ((size_t)bh*NS + s0)*ND;
    const float* wsrc  = out_w + (size_t)h*64*64;
    #pragma unroll
    for (int i = 0; i < 4; i++) {
        int r = lr + i*16;
        float4 x = *(const float4*)(xbase + r*ND + lc);
        float4 w = *(const float4*)(wsrc  + r*64 + lc);
        float* xd = Xs + r*QPA + lc;
        float* wd = Wsm + r*QPA + lc;
        xd[0]=tf32f(x.x); xd[1]=tf32f(x.y); xd[2]=tf32f(x.z); xd[3]=tf32f(x.w);
        wd[0]=tf32f(w.x); wd[1]=tf32f(w.y); wd[2]=tf32f(w.z); wd[3]=tf32f(w.w);
    }
    __syncthreads();
    float acc[4][4] = {};
    #pragma unroll
    for (int kc = 0; kc < 8; kc++) {
        const float* ab = Xs + fr0*QPA + kc*8 + t;
        unsigned a[4];
        a[0]=__float_as_uint(ab[0]);  a[1]=__float_as_uint(ab[8*QPA]);
        a[2]=__float_as_uint(ab[4]);  a[3]=__float_as_uint(ab[8*QPA+4]);
        #pragma unroll
        for (int nt = 0; nt < 4; nt++) {
            const float* bb = Wsm + (wn*32 + nt*8 + g)*QPA + kc*8 + t;
            mma_tf32(acc[nt], a, __float_as_uint(bb[0]), __float_as_uint(bb[4]));
        }
    }
    const float* resid = g_c[which];
    int off = which * 64;
    #pragma unroll
    for (int nt = 0; nt < 4; nt++) {
        int c = wn*32 + nt*8 + 2*t;
        float bx = out_b[h*64+c], by = out_b[h*64+c+1];
        int s0r = s0 + fr0, s1r = s0 + fr0 + 8;
        const float* r0 = resid + ((size_t)bh*NS + s0r)*ND + c;
        const float* r1 = resid + ((size_t)bh*NS + s1r)*ND + c;
        float* d0 = g_comb + ((size_t)bh*NS + s0r)*128 + off + c;
        float* d1 = g_comb + ((size_t)bh*NS + s1r)*128 + off + c;
        *(float2*)d0 = make_float2(acc[nt][0]+bx+r0[0], acc[nt][1]+by+r0[1]);
        *(float2*)d1 = make_float2(acc[nt][2]+bx+r1[0], acc[nt][3]+by+r1[1]);
    }
}

// ---------------- final LN over concat dim (128) — R12 proven ----------------
__global__ void final_ln_kernel(const float* __restrict__ hg, const float* __restrict__ hb,
                                float* __restrict__ out) {
    int row = blockIdx.x * 8 + (threadIdx.x >> 5);
    int lane = threadIdx.x & 31;
    const float* x = g_comb + (size_t)row * 128;
    float v[4], sum = 0.f;
    #pragma unroll
    for (int i=0;i<4;i++){ v[i] = x[lane + i*32]; sum += v[i]; }
    #pragma unroll
    for (int o = 16; o > 0; o >>= 1) sum += __shfl_xor_sync(0xffffffffu, sum, o);
    float mu = sum * (1.f/128.f);
    float sq = 0.f;
    #pragma unroll
    for (int i=0;i<4;i++){ float d = v[i]-mu; sq += d*d; }
    #pragma unroll
    for (int o = 16; o > 0; o >>= 1) sq += __shfl_xor_sync(0xffffffffu, sq, o);
    float rstd = rsqrtf(sq*(1.f/128.f) + 1e-5f);
    int h = (row >> 9) & 15;
    #pragma unroll
    for (int i=0;i<4;i++){
        int c = lane + i*32;
        out[(size_t)row*128 + c] = (v[i]-mu)*rstd*hg[h*128+c] + hb[h*128+c];
    }
}

// ---------------- launch ----------------
extern "C" void kernel_launch(void* const* d_in, const int* in_sizes, int n_in,
                              void* d_out, int out_size) {
    const float* image     = (const float*)d_in[0];
    const float* text      = (const float*)d_in[1];
    const float* img_w     = (const float*)d_in[2];
    const float* img_b     = (const float*)d_in[3];
    const float* img_g     = (const float*)d_in[4];
    const float* img_lb    = (const float*)d_in[5];
    const float* txt_w     = (const float*)d_in[6];
    const float* txt_b     = (const float*)d_in[7];
    const float* txt_g     = (const float*)d_in[8];
    const float* txt_lb    = (const float*)d_in[9];
    const float* i2t_in_w  = (const float*)d_in[10];
    const float* i2t_in_b  = (const float*)d_in[11];
    const float* i2t_out_w = (const float*)d_in[12];
    const float* i2t_out_b = (const float*)d_in[13];
    const float* t2i_in_w  = (const float*)d_in[14];
    const float* t2i_in_b  = (const float*)d_in[15];
    const float* t2i_out_w = (const float*)d_in[16];
    const float* t2i_out_b = (const float*)d_in[17];
    const float* hn_g      = (const float*)d_in[18];
    const float* hn_b      = (const float*)d_in[19];
    float* out = (float*)d_out;

    const int QKV_SMEM  = 3*64*QPA*4;    // 52224 B
    const int ATTN_SMEM = 2*TILE_F*4;    // 71680 B
    static int attrs_set = 0;
    if (!attrs_set) {
        cudaFuncSetAttribute(qkv_tf32_kernel, cudaFuncAttributeMaxDynamicSharedMemorySize, QKV_SMEM);
        cudaFuncSetAttribute(attn_kernel, cudaFuncAttributeMaxDynamicSharedMemorySize, ATTN_SMEM);
        attrs_set = 1;
    }

    dim3 thr(256);
    gemm_tf32_kernel<<<dim3(8,64), thr>>>(image, img_w, img_b, 768, 0);
    gemm_tf32_kernel<<<dim3(8,64), thr>>>(text,  txt_w, txt_b, 512, 1);
    ln_l2_kernel<<<dim3(8192,2), thr>>>(img_g, img_lb, txt_g, txt_lb);
    qkv_tf32_kernel<<<dim3(8,256,2), thr, QKV_SMEM>>>(i2t_in_w, i2t_in_b, t2i_in_w, t2i_in_b);
    attn_kernel<<<dim3(4,256,2), thr, ATTN_SMEM>>>();
    outproj_tf32_kernel<<<dim3(8,256,2), thr>>>(i2t_out_w, i2t_out_b, t2i_out_w, t2i_out_b);
    final_ln_kernel<<<16384, thr>>>(hn_g, hn_b, out);
}